// round 9
// baseline (speedup 1.0000x reference)
#include <cuda_runtime.h>
#include <cstdint>

#define NN 50000
#define EE 800000
#define DD 128

// ---------------- scratch (static device globals; no allocation allowed) ----
__device__ __align__(16) float g_q[NN * DD];
__device__ __align__(16) float g_k[NN * DD];
__device__ __align__(16) float g_v[NN * DD];
__device__ __align__(16) float g_skip[NN * DD];
__device__ __align__(16) float g_h[NN * DD];

// tf32 weights, REPACKED into per-thread mma fragment order (see k_wrepack)
__device__ __align__(16) unsigned g_wt[8 * DD * DD];

__device__ __align__(16) int g_deg[NN];
__device__ __align__(16) int g_off[NN + 2];
__device__ __align__(16) int g_cursor[NN];
__device__ __align__(16) int g_bsum[128];
__device__ __align__(16) int g_boff[128];
__device__ __align__(16) int g_csrc[EE];
__device__ int g_is64;

// ---------------- fused: zero degree array + edge dtype detection -----------
__global__ void k_detect_zero(const int* __restrict__ p) {
    int i = blockIdx.x * blockDim.x + threadIdx.x;
    if (i < NN) g_deg[i] = 0;
    if (blockIdx.x == 0) {
        __shared__ int any;
        if (threadIdx.x == 0) any = 0;
        __syncthreads();
        int nz = 0;
        for (int t = threadIdx.x; t < 1024; t += blockDim.x) nz |= p[2 * t + 1];
        if (nz) any = 1;
        __syncthreads();
        if (threadIdx.x == 0) g_is64 = (any == 0);
    }
}

__device__ __forceinline__ int load_edge(const void* ei, long long idx) {
    int v;
    if (g_is64) v = (int)((const long long*)ei)[idx];
    else        v = ((const int*)ei)[idx];
    return min(max(v, 0), NN - 1);
}

// ---------------- weight conversion + fragment repack ------------------------
// Packed word index within one matrix: t = ((k0g*8 + j)*32 + lane)*4 + c
//   j<4:  b0 for nf = j*4 + c      -> W[k0g*8 + tig][ (j*4+c)*8 + gid ]
//   j>=4: b1 for nf = (j-4)*4 + c  -> W[k0g*8 + tig + 4][ ((j-4)*4+c)*8 + gid ]
__global__ void k_wrepack(
    const float* __restrict__ w0, const float* __restrict__ w1,
    const float* __restrict__ w2, const float* __restrict__ w3,
    const float* __restrict__ w4, const float* __restrict__ w5,
    const float* __restrict__ w6, const float* __restrict__ w7)
{
    int i = blockIdx.x * blockDim.x + threadIdx.x;     // 0 .. 131071
    int m = i >> 14;
    int t = i & 16383;
    int c = t & 3;
    int lane = (t >> 2) & 31;
    int j = (t >> 7) & 7;
    int k0g = t >> 10;
    int gid = lane >> 2, tig = lane & 3;
    int nf = (j & 3) * 4 + c;
    int k = k0g * 8 + tig + ((j >= 4) ? 4 : 0);
    int n = nf * 8 + gid;
    const float* src =
        (m == 0) ? w0 : (m == 1) ? w1 : (m == 2) ? w2 : (m == 3) ? w3 :
        (m == 4) ? w4 : (m == 5) ? w5 : (m == 6) ? w6 : w7;
    float f = src[k * DD + n];
    unsigned u;
    asm("cvt.rna.tf32.f32 %0, %1;" : "=r"(u) : "f"(f));
    g_wt[i] = u;
}

// ---------------- CSR build -------------------------------------------------
__global__ void k_hist(const void* __restrict__ ei) {
    int e = blockIdx.x * blockDim.x + threadIdx.x;
    if (e < EE) atomicAdd(&g_deg[load_edge(ei, (long long)EE + e)], 1);
}

__global__ void k_scan1() {
    __shared__ int sh[512];
    int tid = threadIdx.x;
    int i = blockIdx.x * 512 + tid;
    int v = (i < NN) ? g_deg[i] : 0;
    sh[tid] = v;
    __syncthreads();
    for (int off = 1; off < 512; off <<= 1) {
        int t = 0;
        if (tid >= off) t = sh[tid - off];
        __syncthreads();
        sh[tid] += t;
        __syncthreads();
    }
    if (i < NN) g_off[i] = sh[tid] - v;
    if (tid == 511) g_bsum[blockIdx.x] = sh[511];
}

__global__ void k_scan2(int nb) {
    __shared__ int sh[128];
    int tid = threadIdx.x;
    int v = (tid < nb) ? g_bsum[tid] : 0;
    sh[tid] = v;
    __syncthreads();
    for (int off = 1; off < 128; off <<= 1) {
        int t = 0;
        if (tid >= off) t = sh[tid - off];
        __syncthreads();
        sh[tid] += t;
        __syncthreads();
    }
    g_boff[tid] = sh[tid] - v;
}

__global__ void k_scan3() {
    int i = blockIdx.x * blockDim.x + threadIdx.x;
    if (i < NN) {
        int o = g_off[i] + g_boff[i >> 9];
        g_off[i] = o;
        g_cursor[i] = o;
    }
    if (i == 0) g_off[NN] = EE;
}

__global__ void k_scatter(const void* __restrict__ ei) {
    int e = blockIdx.x * blockDim.x + threadIdx.x;
    if (e < EE) {
        int dst = load_edge(ei, (long long)EE + e);
        int src = load_edge(ei, e);
        int pos = atomicAdd(&g_cursor[dst], 1);
        if (pos < EE) g_csrc[pos] = src;
    }
}

// ---------------- tensor-core projection GEMM (tf32 mma.sync) ---------------
// 128 threads / 4 warps, M-tile 128: warp w owns rows [w*32, w*32+32) x 128
// cols (4 row-groups of 8). Same 8x LDG.128 weight fetch per k-group now
// feeds 32 mmas instead of 16 — halves weight traffic per row, doubles
// tensor work per load batch. Dynamic smem (67.6 KB, padded stride 132).
__global__ void __launch_bounds__(128) k_proj(
    const float* __restrict__ x_in, int wbase,
    const float* __restrict__ bq, const float* __restrict__ bk,
    const float* __restrict__ bv, const float* __restrict__ bs)
{
    extern __shared__ unsigned xs[];           // [128][132] tf32 bits

    const float* x = (x_in != nullptr) ? x_in : g_h;
    int tid = threadIdx.x;
    int row0 = blockIdx.x * 128;

    for (int i = tid; i < 128 * 32; i += 128) { // 32 float4 per row
        int r = i >> 5, c = (i & 31) * 4;
        float4 v = make_float4(0.f, 0.f, 0.f, 0.f);
        int row = row0 + r;
        if (row < NN) v = *(const float4*)(x + row * DD + c);
        unsigned u0, u1, u2, u3;
        asm("cvt.rna.tf32.f32 %0, %1;" : "=r"(u0) : "f"(v.x));
        asm("cvt.rna.tf32.f32 %0, %1;" : "=r"(u1) : "f"(v.y));
        asm("cvt.rna.tf32.f32 %0, %1;" : "=r"(u2) : "f"(v.z));
        asm("cvt.rna.tf32.f32 %0, %1;" : "=r"(u3) : "f"(v.w));
        *(uint4*)(&xs[r * 132 + c]) = make_uint4(u0, u1, u2, u3);
    }
    __syncthreads();

    int warp = tid >> 5, lane = tid & 31;
    int gid = lane >> 2, tig = lane & 3;
    int rA = warp * 32 + gid;                  // rows rA, +8, +16, +24

    for (int m = 0; m < 4; m++) {
        const uint4* Wp = (const uint4*)(g_wt + (wbase + m) * (DD * DD));
        const float* B = (m == 0) ? bq : (m == 1) ? bk : (m == 2) ? bv : bs;
        float* O = (m == 0) ? g_q : (m == 1) ? g_k : (m == 2) ? g_v : g_skip;

        // acc[nf][0..3] = rows (rA,rA+8); acc[nf][4..7] = rows (rA+16,rA+24)
        float acc[16][8];
#pragma unroll
        for (int nf = 0; nf < 16; nf++) {
            float2 bb = *(const float2*)(B + nf * 8 + 2 * tig);
#pragma unroll
            for (int h = 0; h < 4; h++) {
                acc[nf][2 * h] = bb.x;
                acc[nf][2 * h + 1] = bb.y;
            }
        }

#pragma unroll
        for (int k0g = 0; k0g < 16; k0g++) {
            uint4 u[8];
#pragma unroll
            for (int j = 0; j < 8; j++)
                u[j] = Wp[(k0g * 8 + j) * 32 + lane];

            int k0 = k0g * 8;
            unsigned a0 = xs[rA * 132 + k0 + tig];
            unsigned a1 = xs[(rA + 8) * 132 + k0 + tig];
            unsigned a2 = xs[rA * 132 + k0 + tig + 4];
            unsigned a3 = xs[(rA + 8) * 132 + k0 + tig + 4];
            unsigned c0 = xs[(rA + 16) * 132 + k0 + tig];
            unsigned c1 = xs[(rA + 24) * 132 + k0 + tig];
            unsigned c2 = xs[(rA + 16) * 132 + k0 + tig + 4];
            unsigned c3 = xs[(rA + 24) * 132 + k0 + tig + 4];

#pragma unroll
            for (int nf = 0; nf < 16; nf++) {
                int q = nf >> 2, cc = nf & 3;
                unsigned b0 = (cc == 0) ? u[q].x : (cc == 1) ? u[q].y
                            : (cc == 2) ? u[q].z : u[q].w;
                unsigned b1 = (cc == 0) ? u[4 + q].x : (cc == 1) ? u[4 + q].y
                            : (cc == 2) ? u[4 + q].z : u[4 + q].w;
                asm volatile(
                    "mma.sync.aligned.m16n8k8.row.col.f32.tf32.tf32.f32 "
                    "{%0,%1,%2,%3}, {%4,%5,%6,%7}, {%8,%9}, {%0,%1,%2,%3};\n"
                    : "+f"(acc[nf][0]), "+f"(acc[nf][1]),
                      "+f"(acc[nf][2]), "+f"(acc[nf][3])
                    : "r"(a0), "r"(a1), "r"(a2), "r"(a3), "r"(b0), "r"(b1));
                asm volatile(
                    "mma.sync.aligned.m16n8k8.row.col.f32.tf32.tf32.f32 "
                    "{%0,%1,%2,%3}, {%4,%5,%6,%7}, {%8,%9}, {%0,%1,%2,%3};\n"
                    : "+f"(acc[nf][4]), "+f"(acc[nf][5]),
                      "+f"(acc[nf][6]), "+f"(acc[nf][7])
                    : "r"(c0), "r"(c1), "r"(c2), "r"(c3), "r"(b0), "r"(b1));
            }
        }

#pragma unroll
        for (int h = 0; h < 4; h++) {
            int rg = row0 + rA + h * 8;
            if (rg < NN) {
#pragma unroll
                for (int nf = 0; nf < 16; nf++)
                    *(float2*)(O + rg * DD + nf * 8 + 2 * tig) =
                        make_float2(acc[nf][2 * ((h & 1) ? (h >> 1) * 2 + 1 : (h >> 1) * 2)],
                                    acc[nf][2 * ((h & 1) ? (h >> 1) * 2 + 1 : (h >> 1) * 2) + 1]);
            }
        }
    }
}

// ---------------- warp-per-node online-softmax attention + skip ------------
// 4 edges per iteration: 8 outstanding float4 gathers, 4 independent shfl
// chains, merged softmax update.
__global__ void __launch_bounds__(256) k_attn(float* out_ptr) {
    int node = (blockIdx.x * blockDim.x + threadIdx.x) >> 5;
    if (node >= NN) return;
    int lane = threadIdx.x & 31;

    int do_relu = (out_ptr == nullptr);
    float* out = do_relu ? g_h : out_ptr;

    const float4 q4 = *(const float4*)(g_q + node * DD + lane * 4);

    float4 acc = make_float4(0.f, 0.f, 0.f, 0.f);
    float m = -1e30f, s = 0.f;

    int j = g_off[node];
    int end = g_off[node + 1];
    const float SC = 0.17677669529663689f;       // 1/sqrt(32)

    for (; j + 4 <= end; j += 4) {
        int s0 = g_csrc[j], s1 = g_csrc[j + 1];
        int s2 = g_csrc[j + 2], s3 = g_csrc[j + 3];
        const float4 k0 = *(const float4*)(g_k + s0 * DD + lane * 4);
        const float4 k1 = *(const float4*)(g_k + s1 * DD + lane * 4);
        const float4 k2 = *(const float4*)(g_k + s2 * DD + lane * 4);
        const float4 k3 = *(const float4*)(g_k + s3 * DD + lane * 4);
        const float4 v0 = *(const float4*)(g_v + s0 * DD + lane * 4);
        const float4 v1 = *(const float4*)(g_v + s1 * DD + lane * 4);
        const float4 v2 = *(const float4*)(g_v + s2 * DD + lane * 4);
        const float4 v3 = *(const float4*)(g_v + s3 * DD + lane * 4);

        float t0 = q4.x * k0.x + q4.y * k0.y + q4.z * k0.z + q4.w * k0.w;
        float t1 = q4.x * k1.x + q4.y * k1.y + q4.z * k1.z + q4.w * k1.w;
        float t2 = q4.x * k2.x + q4.y * k2.y + q4.z * k2.z + q4.w * k2.w;
        float t3 = q4.x * k3.x + q4.y * k3.y + q4.z * k3.z + q4.w * k3.w;
        t0 += __shfl_xor_sync(0xffffffffu, t0, 1);
        t1 += __shfl_xor_sync(0xffffffffu, t1, 1);
        t2 += __shfl_xor_sync(0xffffffffu, t2, 1);
        t3 += __shfl_xor_sync(0xffffffffu, t3, 1);
        t0 += __shfl_xor_sync(0xffffffffu, t0, 2);
        t1 += __shfl_xor_sync(0xffffffffu, t1, 2);
        t2 += __shfl_xor_sync(0xffffffffu, t2, 2);
        t3 += __shfl_xor_sync(0xffffffffu, t3, 2);
        t0 += __shfl_xor_sync(0xffffffffu, t0, 4);
        t1 += __shfl_xor_sync(0xffffffffu, t1, 4);
        t2 += __shfl_xor_sync(0xffffffffu, t2, 4);
        t3 += __shfl_xor_sync(0xffffffffu, t3, 4);

        float l0 = t0 * SC, l1 = t1 * SC, l2 = t2 * SC, l3 = t3 * SC;
        float nm = fmaxf(fmaxf(m, fmaxf(l0, l1)), fmaxf(l2, l3));
        float fac = __expf(m - nm);
        float e0 = __expf(l0 - nm);
        float e1 = __expf(l1 - nm);
        float e2 = __expf(l2 - nm);
        float e3 = __expf(l3 - nm);
        s = s * fac + e0 + e1 + e2 + e3;
        acc.x = acc.x * fac + v0.x * e0 + v1.x * e1 + v2.x * e2 + v3.x * e3;
        acc.y = acc.y * fac + v0.y * e0 + v1.y * e1 + v2.y * e2 + v3.y * e3;
        acc.z = acc.z * fac + v0.z * e0 + v1.z * e1 + v2.z * e2 + v3.z * e3;
        acc.w = acc.w * fac + v0.w * e0 + v1.w * e1 + v2.w * e2 + v3.w * e3;
        m = nm;
    }
    for (; j < end; ++j) {
        int s0 = g_csrc[j];
        const float4 k0 = *(const float4*)(g_k + s0 * DD + lane * 4);
        const float4 v0 = *(const float4*)(g_v + s0 * DD + lane * 4);
        float t0 = q4.x * k0.x + q4.y * k0.y + q4.z * k0.z + q4.w * k0.w;
        t0 += __shfl_xor_sync(0xffffffffu, t0, 1);
        t0 += __shfl_xor_sync(0xffffffffu, t0, 2);
        t0 += __shfl_xor_sync(0xffffffffu, t0, 4);
        float l0 = t0 * SC;
        float nm = fmaxf(m, l0);
        float fac = __expf(m - nm);
        float e0 = __expf(l0 - nm);
        s = s * fac + e0;
        acc.x = acc.x * fac + v0.x * e0;
        acc.y = acc.y * fac + v0.y * e0;
        acc.z = acc.z * fac + v0.z * e0;
        acc.w = acc.w * fac + v0.w * e0;
        m = nm;
    }

    float inv = 1.f / (s + 1e-16f);
    const float4 sk = *(const float4*)(g_skip + node * DD + lane * 4);
    float4 o;
    o.x = acc.x * inv + sk.x;
    o.y = acc.y * inv + sk.y;
    o.z = acc.z * inv + sk.z;
    o.w = acc.w * inv + sk.w;
    if (do_relu) {
        o.x = fmaxf(o.x, 0.f);
        o.y = fmaxf(o.y, 0.f);
        o.z = fmaxf(o.z, 0.f);
        o.w = fmaxf(o.w, 0.f);
    }
    *(float4*)(out + node * DD + lane * 4) = o;
}

// ---------------- launch ----------------------------------------------------
extern "C" void kernel_launch(void* const* d_in, const int* in_sizes, int n_in,
                              void* d_out, int out_size) {
    const float* x = (const float*)d_in[0];
    const void* ei = d_in[1];    // int32 or int64 — detected on device
    float* out = (float*)d_out;

    const int NB_SCAN1 = (NN + 511) / 512;       // 98
    const int PROJ_GRID = (NN + 127) / 128;      // 391
    const int ATTN_GRID = (NN + 7) / 8;          // 6250
    const int PROJ_SMEM = 128 * 132 * 4;         // 67584 B

    cudaFuncSetAttribute(k_proj,
        cudaFuncAttributeMaxDynamicSharedMemorySize, PROJ_SMEM);

    k_detect_zero<<<(NN + 255) / 256, 256>>>((const int*)ei);      // 0
    k_wrepack<<<512, 256>>>(                                       // 1
        (const float*)d_in[2], (const float*)d_in[4],
        (const float*)d_in[6], (const float*)d_in[8],
        (const float*)d_in[10], (const float*)d_in[12],
        (const float*)d_in[14], (const float*)d_in[16]);
    k_hist<<<(EE + 255) / 256, 256>>>(ei);                         // 2
    k_proj<<<PROJ_GRID, 128, PROJ_SMEM>>>(x, 0,                    // 3 (profiled)
        (const float*)d_in[3], (const float*)d_in[5],
        (const float*)d_in[7], (const float*)d_in[9]);
    k_scan1<<<NB_SCAN1, 512>>>();                                  // 4
    k_scan2<<<1, 128>>>(NB_SCAN1);                                 // 5
    k_scan3<<<(NN + 255) / 256, 256>>>();                          // 6
    k_scatter<<<(EE + 255) / 256, 256>>>(ei);                      // 7
    k_attn<<<ATTN_GRID, 256>>>(nullptr);                           // 8: g_h + relu
    k_proj<<<PROJ_GRID, 128, PROJ_SMEM>>>(nullptr, 4,              // 9
        (const float*)d_in[11], (const float*)d_in[13],
        (const float*)d_in[15], (const float*)d_in[17]);
    k_attn<<<ATTN_GRID, 256>>>(out);                               // 10
}

// round 11
// speedup vs baseline: 1.1066x; 1.1066x over previous
#include <cuda_runtime.h>
#include <cstdint>

#define NN 50000
#define EE 800000
#define DD 128

// ---------------- scratch (static device globals; no allocation allowed) ----
__device__ __align__(16) float g_q[NN * DD];
__device__ __align__(16) float g_k[NN * DD];
__device__ __align__(16) float g_v[NN * DD];
__device__ __align__(16) float g_skip[NN * DD];
__device__ __align__(16) float g_h[NN * DD];

// tf32 weights, REPACKED into per-thread mma fragment order (see k_wrepack)
__device__ __align__(16) unsigned g_wt[8 * DD * DD];

__device__ __align__(16) int g_deg[NN];
__device__ __align__(16) int g_off[NN + 2];
__device__ __align__(16) int g_cursor[NN];
__device__ __align__(16) int g_bsum[128];
__device__ __align__(16) int g_boff[128];
__device__ __align__(16) int g_csrc[EE];
__device__ int g_is64;

// ---------------- fused: zero degree array + edge dtype detection -----------
__global__ void k_detect_zero(const int* __restrict__ p) {
    int i = blockIdx.x * blockDim.x + threadIdx.x;
    if (i < NN) g_deg[i] = 0;
    if (blockIdx.x == 0) {
        __shared__ int any;
        if (threadIdx.x == 0) any = 0;
        __syncthreads();
        int nz = 0;
        for (int t = threadIdx.x; t < 1024; t += blockDim.x) nz |= p[2 * t + 1];
        if (nz) any = 1;
        __syncthreads();
        if (threadIdx.x == 0) g_is64 = (any == 0);
    }
}

__device__ __forceinline__ int load_edge(const void* ei, long long idx) {
    int v;
    if (g_is64) v = (int)((const long long*)ei)[idx];
    else        v = ((const int*)ei)[idx];
    return min(max(v, 0), NN - 1);
}

// ---------------- weight conversion + fragment repack ------------------------
// Packed word index within one matrix: t = ((k0g*8 + j)*32 + lane)*4 + c
//   j<4:  b0 for nf = j*4 + c      -> W[k0g*8 + tig][ (j*4+c)*8 + gid ]
//   j>=4: b1 for nf = (j-4)*4 + c  -> W[k0g*8 + tig + 4][ ((j-4)*4+c)*8 + gid ]
__global__ void k_wrepack(
    const float* __restrict__ w0, const float* __restrict__ w1,
    const float* __restrict__ w2, const float* __restrict__ w3,
    const float* __restrict__ w4, const float* __restrict__ w5,
    const float* __restrict__ w6, const float* __restrict__ w7)
{
    int i = blockIdx.x * blockDim.x + threadIdx.x;     // 0 .. 131071
    int m = i >> 14;
    int t = i & 16383;
    int c = t & 3;
    int lane = (t >> 2) & 31;
    int j = (t >> 7) & 7;
    int k0g = t >> 10;
    int gid = lane >> 2, tig = lane & 3;
    int nf = (j & 3) * 4 + c;
    int k = k0g * 8 + tig + ((j >= 4) ? 4 : 0);
    int n = nf * 8 + gid;
    const float* src =
        (m == 0) ? w0 : (m == 1) ? w1 : (m == 2) ? w2 : (m == 3) ? w3 :
        (m == 4) ? w4 : (m == 5) ? w5 : (m == 6) ? w6 : w7;
    float f = src[k * DD + n];
    unsigned u;
    asm("cvt.rna.tf32.f32 %0, %1;" : "=r"(u) : "f"(f));
    g_wt[i] = u;
}

// ---------------- CSR build -------------------------------------------------
__global__ void k_hist(const void* __restrict__ ei) {
    int e = blockIdx.x * blockDim.x + threadIdx.x;
    if (e < EE) atomicAdd(&g_deg[load_edge(ei, (long long)EE + e)], 1);
}

__global__ void k_scan1() {
    __shared__ int sh[512];
    int tid = threadIdx.x;
    int i = blockIdx.x * 512 + tid;
    int v = (i < NN) ? g_deg[i] : 0;
    sh[tid] = v;
    __syncthreads();
    for (int off = 1; off < 512; off <<= 1) {
        int t = 0;
        if (tid >= off) t = sh[tid - off];
        __syncthreads();
        sh[tid] += t;
        __syncthreads();
    }
    if (i < NN) g_off[i] = sh[tid] - v;
    if (tid == 511) g_bsum[blockIdx.x] = sh[511];
}

__global__ void k_scan2(int nb) {
    __shared__ int sh[128];
    int tid = threadIdx.x;
    int v = (tid < nb) ? g_bsum[tid] : 0;
    sh[tid] = v;
    __syncthreads();
    for (int off = 1; off < 128; off <<= 1) {
        int t = 0;
        if (tid >= off) t = sh[tid - off];
        __syncthreads();
        sh[tid] += t;
        __syncthreads();
    }
    g_boff[tid] = sh[tid] - v;
}

__global__ void k_scan3() {
    int i = blockIdx.x * blockDim.x + threadIdx.x;
    if (i < NN) {
        int o = g_off[i] + g_boff[i >> 9];
        g_off[i] = o;
        g_cursor[i] = o;
    }
    if (i == 0) g_off[NN] = EE;
}

__global__ void k_scatter(const void* __restrict__ ei) {
    int e = blockIdx.x * blockDim.x + threadIdx.x;
    if (e < EE) {
        int dst = load_edge(ei, (long long)EE + e);
        int src = load_edge(ei, e);
        int pos = atomicAdd(&g_cursor[dst], 1);
        if (pos < EE) g_csrc[pos] = src;
    }
}

// ---------------- tensor-core projection GEMM (tf32 mma.sync) ---------------
// 128 threads / 4 warps, M-tile 64 (round-7 geometry). NEW: weight fragments
// staged per-block in shared memory (64 KB, coalesced copy) — 4x less L1/L2
// traffic, and inner-loop fragment reads become 29-cycle conflict-free
// LDS.128 instead of ~234-cycle L2 LDGs. smem: xs 33.8 KB + ws 64 KB.
__global__ void __launch_bounds__(128) k_proj(
    const float* __restrict__ x_in, int wbase,
    const float* __restrict__ bq, const float* __restrict__ bk,
    const float* __restrict__ bv, const float* __restrict__ bs)
{
    extern __shared__ unsigned sm[];
    unsigned* xs = sm;                              // [64][132] tf32 bits
    uint4* ws = (uint4*)(sm + 64 * 132);            // 4096 uint4 = 64 KB

    const float* x = (x_in != nullptr) ? x_in : g_h;
    int tid = threadIdx.x;
    int row0 = blockIdx.x * 64;

    for (int i = tid; i < 64 * 32; i += 128) {      // 32 float4 per row
        int r = i >> 5, c = (i & 31) * 4;
        float4 v = make_float4(0.f, 0.f, 0.f, 0.f);
        int row = row0 + r;
        if (row < NN) v = *(const float4*)(x + row * DD + c);
        unsigned u0, u1, u2, u3;
        asm("cvt.rna.tf32.f32 %0, %1;" : "=r"(u0) : "f"(v.x));
        asm("cvt.rna.tf32.f32 %0, %1;" : "=r"(u1) : "f"(v.y));
        asm("cvt.rna.tf32.f32 %0, %1;" : "=r"(u2) : "f"(v.z));
        asm("cvt.rna.tf32.f32 %0, %1;" : "=r"(u3) : "f"(v.w));
        *(uint4*)(&xs[r * 132 + c]) = make_uint4(u0, u1, u2, u3);
    }

    int warp = tid >> 5, lane = tid & 31;
    int gid = lane >> 2, tig = lane & 3;
    int rA = warp * 16 + gid;

    for (int m = 0; m < 4; m++) {
        const uint4* Wp = (const uint4*)(g_wt + (wbase + m) * (DD * DD));
        const float* B = (m == 0) ? bq : (m == 1) ? bk : (m == 2) ? bv : bs;
        float* O = (m == 0) ? g_q : (m == 1) ? g_k : (m == 2) ? g_v : g_skip;

        __syncthreads();                            // ws free of prior readers
#pragma unroll 8
        for (int i = tid; i < 4096; i += 128) ws[i] = Wp[i];
        __syncthreads();                            // ws (and xs on m=0) ready

        float acc[16][4];
#pragma unroll
        for (int nf = 0; nf < 16; nf++) {
            float2 bb = *(const float2*)(B + nf * 8 + 2 * tig);
            acc[nf][0] = bb.x; acc[nf][1] = bb.y;
            acc[nf][2] = bb.x; acc[nf][3] = bb.y;
        }

#pragma unroll
        for (int k0g = 0; k0g < 16; k0g++) {
            int k0 = k0g * 8;
            unsigned a0 = xs[rA * 132 + k0 + tig];
            unsigned a1 = xs[(rA + 8) * 132 + k0 + tig];
            unsigned a2 = xs[rA * 132 + k0 + tig + 4];
            unsigned a3 = xs[(rA + 8) * 132 + k0 + tig + 4];

#pragma unroll
            for (int q = 0; q < 4; q++) {
                uint4 ulo = ws[(k0g * 8 + q) * 32 + lane];       // LDS.128
                uint4 uhi = ws[(k0g * 8 + 4 + q) * 32 + lane];   // LDS.128
#pragma unroll
                for (int cc = 0; cc < 4; cc++) {
                    int nf = q * 4 + cc;
                    unsigned b0 = (cc == 0) ? ulo.x : (cc == 1) ? ulo.y
                                : (cc == 2) ? ulo.z : ulo.w;
                    unsigned b1 = (cc == 0) ? uhi.x : (cc == 1) ? uhi.y
                                : (cc == 2) ? uhi.z : uhi.w;
                    asm volatile(
                        "mma.sync.aligned.m16n8k8.row.col.f32.tf32.tf32.f32 "
                        "{%0,%1,%2,%3}, {%4,%5,%6,%7}, {%8,%9}, {%0,%1,%2,%3};\n"
                        : "+f"(acc[nf][0]), "+f"(acc[nf][1]),
                          "+f"(acc[nf][2]), "+f"(acc[nf][3])
                        : "r"(a0), "r"(a1), "r"(a2), "r"(a3), "r"(b0), "r"(b1));
                }
            }
        }

        int rg = row0 + rA;
#pragma unroll
        for (int nf = 0; nf < 16; nf++) {
            if (rg < NN)
                *(float2*)(O + rg * DD + nf * 8 + 2 * tig) =
                    make_float2(acc[nf][0], acc[nf][1]);
            if (rg + 8 < NN)
                *(float2*)(O + (rg + 8) * DD + nf * 8 + 2 * tig) =
                    make_float2(acc[nf][2], acc[nf][3]);
        }
    }
}

// ---------------- warp-per-node online-softmax attention + skip ------------
// 4 edges per iteration: 8 outstanding float4 gathers, 4 independent shfl
// chains, merged softmax update.
__global__ void __launch_bounds__(256) k_attn(float* out_ptr) {
    int node = (blockIdx.x * blockDim.x + threadIdx.x) >> 5;
    if (node >= NN) return;
    int lane = threadIdx.x & 31;

    int do_relu = (out_ptr == nullptr);
    float* out = do_relu ? g_h : out_ptr;

    const float4 q4 = *(const float4*)(g_q + node * DD + lane * 4);

    float4 acc = make_float4(0.f, 0.f, 0.f, 0.f);
    float m = -1e30f, s = 0.f;

    int j = g_off[node];
    int end = g_off[node + 1];
    const float SC = 0.17677669529663689f;       // 1/sqrt(32)

    for (; j + 4 <= end; j += 4) {
        int s0 = g_csrc[j], s1 = g_csrc[j + 1];
        int s2 = g_csrc[j + 2], s3 = g_csrc[j + 3];
        const float4 k0 = *(const float4*)(g_k + s0 * DD + lane * 4);
        const float4 k1 = *(const float4*)(g_k + s1 * DD + lane * 4);
        const float4 k2 = *(const float4*)(g_k + s2 * DD + lane * 4);
        const float4 k3 = *(const float4*)(g_k + s3 * DD + lane * 4);
        const float4 v0 = *(const float4*)(g_v + s0 * DD + lane * 4);
        const float4 v1 = *(const float4*)(g_v + s1 * DD + lane * 4);
        const float4 v2 = *(const float4*)(g_v + s2 * DD + lane * 4);
        const float4 v3 = *(const float4*)(g_v + s3 * DD + lane * 4);

        float t0 = q4.x * k0.x + q4.y * k0.y + q4.z * k0.z + q4.w * k0.w;
        float t1 = q4.x * k1.x + q4.y * k1.y + q4.z * k1.z + q4.w * k1.w;
        float t2 = q4.x * k2.x + q4.y * k2.y + q4.z * k2.z + q4.w * k2.w;
        float t3 = q4.x * k3.x + q4.y * k3.y + q4.z * k3.z + q4.w * k3.w;
        t0 += __shfl_xor_sync(0xffffffffu, t0, 1);
        t1 += __shfl_xor_sync(0xffffffffu, t1, 1);
        t2 += __shfl_xor_sync(0xffffffffu, t2, 1);
        t3 += __shfl_xor_sync(0xffffffffu, t3, 1);
        t0 += __shfl_xor_sync(0xffffffffu, t0, 2);
        t1 += __shfl_xor_sync(0xffffffffu, t1, 2);
        t2 += __shfl_xor_sync(0xffffffffu, t2, 2);
        t3 += __shfl_xor_sync(0xffffffffu, t3, 2);
        t0 += __shfl_xor_sync(0xffffffffu, t0, 4);
        t1 += __shfl_xor_sync(0xffffffffu, t1, 4);
        t2 += __shfl_xor_sync(0xffffffffu, t2, 4);
        t3 += __shfl_xor_sync(0xffffffffu, t3, 4);

        float l0 = t0 * SC, l1 = t1 * SC, l2 = t2 * SC, l3 = t3 * SC;
        float nm = fmaxf(fmaxf(m, fmaxf(l0, l1)), fmaxf(l2, l3));
        float fac = __expf(m - nm);
        float e0 = __expf(l0 - nm);
        float e1 = __expf(l1 - nm);
        float e2 = __expf(l2 - nm);
        float e3 = __expf(l3 - nm);
        s = s * fac + e0 + e1 + e2 + e3;
        acc.x = acc.x * fac + v0.x * e0 + v1.x * e1 + v2.x * e2 + v3.x * e3;
        acc.y = acc.y * fac + v0.y * e0 + v1.y * e1 + v2.y * e2 + v3.y * e3;
        acc.z = acc.z * fac + v0.z * e0 + v1.z * e1 + v2.z * e2 + v3.z * e3;
        acc.w = acc.w * fac + v0.w * e0 + v1.w * e1 + v2.w * e2 + v3.w * e3;
        m = nm;
    }
    for (; j < end; ++j) {
        int s0 = g_csrc[j];
        const float4 k0 = *(const float4*)(g_k + s0 * DD + lane * 4);
        const float4 v0 = *(const float4*)(g_v + s0 * DD + lane * 4);
        float t0 = q4.x * k0.x + q4.y * k0.y + q4.z * k0.z + q4.w * k0.w;
        t0 += __shfl_xor_sync(0xffffffffu, t0, 1);
        t0 += __shfl_xor_sync(0xffffffffu, t0, 2);
        t0 += __shfl_xor_sync(0xffffffffu, t0, 4);
        float l0 = t0 * SC;
        float nm = fmaxf(m, l0);
        float fac = __expf(m - nm);
        float e0 = __expf(l0 - nm);
        s = s * fac + e0;
        acc.x = acc.x * fac + v0.x * e0;
        acc.y = acc.y * fac + v0.y * e0;
        acc.z = acc.z * fac + v0.z * e0;
        acc.w = acc.w * fac + v0.w * e0;
        m = nm;
    }

    float inv = 1.f / (s + 1e-16f);
    const float4 sk = *(const float4*)(g_skip + node * DD + lane * 4);
    float4 o;
    o.x = acc.x * inv + sk.x;
    o.y = acc.y * inv + sk.y;
    o.z = acc.z * inv + sk.z;
    o.w = acc.w * inv + sk.w;
    if (do_relu) {
        o.x = fmaxf(o.x, 0.f);
        o.y = fmaxf(o.y, 0.f);
        o.z = fmaxf(o.z, 0.f);
        o.w = fmaxf(o.w, 0.f);
    }
    *(float4*)(out + node * DD + lane * 4) = o;
}

// ---------------- launch ----------------------------------------------------
extern "C" void kernel_launch(void* const* d_in, const int* in_sizes, int n_in,
                              void* d_out, int out_size) {
    const float* x = (const float*)d_in[0];
    const void* ei = d_in[1];    // int32 or int64 — detected on device
    float* out = (float*)d_out;

    const int NB_SCAN1 = (NN + 511) / 512;       // 98
    const int PROJ_GRID = (NN + 63) / 64;        // 782
    const int ATTN_GRID = (NN + 7) / 8;          // 6250
    const int PROJ_SMEM = 64 * 132 * 4 + 64 * 1024;   // 33792 + 65536 = 99328 B

    cudaFuncSetAttribute(k_proj,
        cudaFuncAttributeMaxDynamicSharedMemorySize, PROJ_SMEM);

    k_detect_zero<<<(NN + 255) / 256, 256>>>((const int*)ei);      // 0
    k_wrepack<<<512, 256>>>(                                       // 1
        (const float*)d_in[2], (const float*)d_in[4],
        (const float*)d_in[6], (const float*)d_in[8],
        (const float*)d_in[10], (const float*)d_in[12],
        (const float*)d_in[14], (const float*)d_in[16]);
    k_hist<<<(EE + 255) / 256, 256>>>(ei);                         // 2
    k_proj<<<PROJ_GRID, 128, PROJ_SMEM>>>(x, 0,                    // 3 (profiled)
        (const float*)d_in[3], (const float*)d_in[5],
        (const float*)d_in[7], (const float*)d_in[9]);
    k_scan1<<<NB_SCAN1, 512>>>();                                  // 4
    k_scan2<<<1, 128>>>(NB_SCAN1);                                 // 5
    k_scan3<<<(NN + 255) / 256, 256>>>();                          // 6
    k_scatter<<<(EE + 255) / 256, 256>>>(ei);                      // 7
    k_attn<<<ATTN_GRID, 256>>>(nullptr);                           // 8: g_h + relu
    k_proj<<<PROJ_GRID, 128, PROJ_SMEM>>>(nullptr, 4,              // 9
        (const float*)d_in[11], (const float*)d_in[13],
        (const float*)d_in[15], (const float*)d_in[17]);
    k_attn<<<ATTN_GRID, 256>>>(out);                               // 10
}

// round 13
// speedup vs baseline: 1.3644x; 1.2330x over previous
#include <cuda_runtime.h>
#include <cstdint>

#define NN 50000
#define EE 800000
#define DD 128

// ---------------- scratch (static device globals; no allocation allowed) ----
__device__ __align__(16) float g_q[NN * DD];
__device__ __align__(16) float g_k[NN * DD];
__device__ __align__(16) float g_v[NN * DD];
__device__ __align__(16) float g_skip[NN * DD];
__device__ __align__(16) float g_h[NN * DD];

// tf32 weights, REPACKED into per-thread mma fragment order (see k_wrepack)
__device__ __align__(16) unsigned g_wt[8 * DD * DD];

__device__ __align__(16) int g_deg[NN];
__device__ __align__(16) int g_off[NN + 2];
__device__ __align__(16) int g_cursor[NN];
__device__ __align__(16) int g_bsum[128];
__device__ __align__(16) int g_boff[128];
__device__ __align__(16) int g_csrc[EE];
__device__ int g_is64;

// ---------------- fused: zero degree array + edge dtype detection -----------
__global__ void k_detect_zero(const int* __restrict__ p) {
    int i = blockIdx.x * blockDim.x + threadIdx.x;
    if (i < NN) g_deg[i] = 0;
    if (blockIdx.x == 0) {
        __shared__ int any;
        if (threadIdx.x == 0) any = 0;
        __syncthreads();
        int nz = 0;
        for (int t = threadIdx.x; t < 1024; t += blockDim.x) nz |= p[2 * t + 1];
        if (nz) any = 1;
        __syncthreads();
        if (threadIdx.x == 0) g_is64 = (any == 0);
    }
}

__device__ __forceinline__ int load_edge(const void* ei, long long idx) {
    int v;
    if (g_is64) v = (int)((const long long*)ei)[idx];
    else        v = ((const int*)ei)[idx];
    return min(max(v, 0), NN - 1);
}

// ---------------- weight conversion + fragment repack ------------------------
// Packed word index within one matrix: t = ((k0g*8 + j)*32 + lane)*4 + c
//   j<4:  b0 for nf = j*4 + c      -> W[k0g*8 + tig][ (j*4+c)*8 + gid ]
//   j>=4: b1 for nf = (j-4)*4 + c  -> W[k0g*8 + tig + 4][ ((j-4)*4+c)*8 + gid ]
__global__ void k_wrepack(
    const float* __restrict__ w0, const float* __restrict__ w1,
    const float* __restrict__ w2, const float* __restrict__ w3,
    const float* __restrict__ w4, const float* __restrict__ w5,
    const float* __restrict__ w6, const float* __restrict__ w7)
{
    int i = blockIdx.x * blockDim.x + threadIdx.x;     // 0 .. 131071
    int m = i >> 14;
    int t = i & 16383;
    int c = t & 3;
    int lane = (t >> 2) & 31;
    int j = (t >> 7) & 7;
    int k0g = t >> 10;
    int gid = lane >> 2, tig = lane & 3;
    int nf = (j & 3) * 4 + c;
    int k = k0g * 8 + tig + ((j >= 4) ? 4 : 0);
    int n = nf * 8 + gid;
    const float* src =
        (m == 0) ? w0 : (m == 1) ? w1 : (m == 2) ? w2 : (m == 3) ? w3 :
        (m == 4) ? w4 : (m == 5) ? w5 : (m == 6) ? w6 : w7;
    float f = src[k * DD + n];
    unsigned u;
    asm("cvt.rna.tf32.f32 %0, %1;" : "=r"(u) : "f"(f));
    g_wt[i] = u;
}

// ---------------- CSR build -------------------------------------------------
__global__ void k_hist(const void* __restrict__ ei) {
    int e = blockIdx.x * blockDim.x + threadIdx.x;
    if (e < EE) atomicAdd(&g_deg[load_edge(ei, (long long)EE + e)], 1);
}

__global__ void k_scan1() {
    __shared__ int sh[512];
    int tid = threadIdx.x;
    int i = blockIdx.x * 512 + tid;
    int v = (i < NN) ? g_deg[i] : 0;
    sh[tid] = v;
    __syncthreads();
    for (int off = 1; off < 512; off <<= 1) {
        int t = 0;
        if (tid >= off) t = sh[tid - off];
        __syncthreads();
        sh[tid] += t;
        __syncthreads();
    }
    if (i < NN) g_off[i] = sh[tid] - v;
    if (tid == 511) g_bsum[blockIdx.x] = sh[511];
}

__global__ void k_scan2(int nb) {
    __shared__ int sh[128];
    int tid = threadIdx.x;
    int v = (tid < nb) ? g_bsum[tid] : 0;
    sh[tid] = v;
    __syncthreads();
    for (int off = 1; off < 128; off <<= 1) {
        int t = 0;
        if (tid >= off) t = sh[tid - off];
        __syncthreads();
        sh[tid] += t;
        __syncthreads();
    }
    g_boff[tid] = sh[tid] - v;
}

__global__ void k_scan3() {
    int i = blockIdx.x * blockDim.x + threadIdx.x;
    if (i < NN) {
        int o = g_off[i] + g_boff[i >> 9];
        g_off[i] = o;
        g_cursor[i] = o;
    }
    if (i == 0) g_off[NN] = EE;
}

__global__ void k_scatter(const void* __restrict__ ei) {
    int e = blockIdx.x * blockDim.x + threadIdx.x;
    if (e < EE) {
        int dst = load_edge(ei, (long long)EE + e);
        int src = load_edge(ei, e);
        int pos = atomicAdd(&g_cursor[dst], 1);
        if (pos < EE) g_csrc[pos] = src;
    }
}

// ---------------- tensor-core projection GEMM (tf32 mma.sync) ---------------
// Round-7 geometry with MATRIX SPLIT across blockIdx.y: grid (782, 4), each
// block computes ONE matrix for one 64-row tile. 4x fewer regs of live acc
// window -> __launch_bounds__(128, 4) pins >=4 blocks/SM (16 warps) for
// latency hiding. B-frags: 8x coalesced LDG.128 per k-group (L1-hot).
__global__ void __launch_bounds__(128, 4) k_proj(
    const float* __restrict__ x_in, int wbase,
    const float* __restrict__ bq, const float* __restrict__ bk,
    const float* __restrict__ bv, const float* __restrict__ bs)
{
    __shared__ unsigned xs[64 * 132];          // tf32 bits, padded stride

    const float* x = (x_in != nullptr) ? x_in : g_h;
    int tid = threadIdx.x;
    int row0 = blockIdx.x * 64;
    int m = blockIdx.y;

    for (int i = tid; i < 64 * 32; i += 128) { // 32 float4 per row
        int r = i >> 5, c = (i & 31) * 4;
        float4 v = make_float4(0.f, 0.f, 0.f, 0.f);
        int row = row0 + r;
        if (row < NN) v = *(const float4*)(x + row * DD + c);
        unsigned u0, u1, u2, u3;
        asm("cvt.rna.tf32.f32 %0, %1;" : "=r"(u0) : "f"(v.x));
        asm("cvt.rna.tf32.f32 %0, %1;" : "=r"(u1) : "f"(v.y));
        asm("cvt.rna.tf32.f32 %0, %1;" : "=r"(u2) : "f"(v.z));
        asm("cvt.rna.tf32.f32 %0, %1;" : "=r"(u3) : "f"(v.w));
        *(uint4*)(&xs[r * 132 + c]) = make_uint4(u0, u1, u2, u3);
    }
    __syncthreads();

    int warp = tid >> 5, lane = tid & 31;
    int gid = lane >> 2, tig = lane & 3;
    int rA = warp * 16 + gid;

    const uint4* Wp = (const uint4*)(g_wt + (wbase + m) * (DD * DD));
    const float* B = (m == 0) ? bq : (m == 1) ? bk : (m == 2) ? bv : bs;
    float* O = (m == 0) ? g_q : (m == 1) ? g_k : (m == 2) ? g_v : g_skip;

    float acc[16][4];
#pragma unroll
    for (int nf = 0; nf < 16; nf++) {
        float2 bb = *(const float2*)(B + nf * 8 + 2 * tig);
        acc[nf][0] = bb.x; acc[nf][1] = bb.y;
        acc[nf][2] = bb.x; acc[nf][3] = bb.y;
    }

#pragma unroll
    for (int k0g = 0; k0g < 16; k0g++) {
        uint4 u[8];
#pragma unroll
        for (int j = 0; j < 8; j++)
            u[j] = Wp[(k0g * 8 + j) * 32 + lane];

        int k0 = k0g * 8;
        unsigned a0 = xs[rA * 132 + k0 + tig];
        unsigned a1 = xs[(rA + 8) * 132 + k0 + tig];
        unsigned a2 = xs[rA * 132 + k0 + tig + 4];
        unsigned a3 = xs[(rA + 8) * 132 + k0 + tig + 4];

#pragma unroll
        for (int nf = 0; nf < 16; nf++) {
            int q = nf >> 2, cc = nf & 3;
            unsigned b0 = (cc == 0) ? u[q].x : (cc == 1) ? u[q].y
                        : (cc == 2) ? u[q].z : u[q].w;
            unsigned b1 = (cc == 0) ? u[4 + q].x : (cc == 1) ? u[4 + q].y
                        : (cc == 2) ? u[4 + q].z : u[4 + q].w;
            asm volatile(
                "mma.sync.aligned.m16n8k8.row.col.f32.tf32.tf32.f32 "
                "{%0,%1,%2,%3}, {%4,%5,%6,%7}, {%8,%9}, {%0,%1,%2,%3};\n"
                : "+f"(acc[nf][0]), "+f"(acc[nf][1]),
                  "+f"(acc[nf][2]), "+f"(acc[nf][3])
                : "r"(a0), "r"(a1), "r"(a2), "r"(a3), "r"(b0), "r"(b1));
        }
    }

    int rg = row0 + rA;
#pragma unroll
    for (int nf = 0; nf < 16; nf++) {
        if (rg < NN)
            *(float2*)(O + rg * DD + nf * 8 + 2 * tig) =
                make_float2(acc[nf][0], acc[nf][1]);
        if (rg + 8 < NN)
            *(float2*)(O + (rg + 8) * DD + nf * 8 + 2 * tig) =
                make_float2(acc[nf][2], acc[nf][3]);
    }
}

// ---------------- warp-per-node online-softmax attention + skip ------------
// 2 edges per iteration (round-7 best variant).
__global__ void __launch_bounds__(256) k_attn(float* out_ptr) {
    int node = (blockIdx.x * blockDim.x + threadIdx.x) >> 5;
    if (node >= NN) return;
    int lane = threadIdx.x & 31;

    int do_relu = (out_ptr == nullptr);
    float* out = do_relu ? g_h : out_ptr;

    const float4 q4 = *(const float4*)(g_q + node * DD + lane * 4);

    float4 acc = make_float4(0.f, 0.f, 0.f, 0.f);
    float m = -1e30f, s = 0.f;

    int j = g_off[node];
    int end = g_off[node + 1];
    const float SC = 0.17677669529663689f;       // 1/sqrt(32)

    for (; j + 2 <= end; j += 2) {
        int s0 = g_csrc[j];
        int s1 = g_csrc[j + 1];
        const float4 k0 = *(const float4*)(g_k + s0 * DD + lane * 4);
        const float4 v0 = *(const float4*)(g_v + s0 * DD + lane * 4);
        const float4 k1 = *(const float4*)(g_k + s1 * DD + lane * 4);
        const float4 v1 = *(const float4*)(g_v + s1 * DD + lane * 4);

        float t0 = q4.x * k0.x + q4.y * k0.y + q4.z * k0.z + q4.w * k0.w;
        float t1 = q4.x * k1.x + q4.y * k1.y + q4.z * k1.z + q4.w * k1.w;
        t0 += __shfl_xor_sync(0xffffffffu, t0, 1);
        t1 += __shfl_xor_sync(0xffffffffu, t1, 1);
        t0 += __shfl_xor_sync(0xffffffffu, t0, 2);
        t1 += __shfl_xor_sync(0xffffffffu, t1, 2);
        t0 += __shfl_xor_sync(0xffffffffu, t0, 4);
        t1 += __shfl_xor_sync(0xffffffffu, t1, 4);

        float l0 = t0 * SC;
        float l1 = t1 * SC;
        float nm = fmaxf(m, fmaxf(l0, l1));
        float fac = __expf(m - nm);
        float e0 = __expf(l0 - nm);
        float e1 = __expf(l1 - nm);
        s = s * fac + e0 + e1;
        acc.x = acc.x * fac + v0.x * e0 + v1.x * e1;
        acc.y = acc.y * fac + v0.y * e0 + v1.y * e1;
        acc.z = acc.z * fac + v0.z * e0 + v1.z * e1;
        acc.w = acc.w * fac + v0.w * e0 + v1.w * e1;
        m = nm;
    }
    if (j < end) {
        int s0 = g_csrc[j];
        const float4 k0 = *(const float4*)(g_k + s0 * DD + lane * 4);
        const float4 v0 = *(const float4*)(g_v + s0 * DD + lane * 4);
        float t0 = q4.x * k0.x + q4.y * k0.y + q4.z * k0.z + q4.w * k0.w;
        t0 += __shfl_xor_sync(0xffffffffu, t0, 1);
        t0 += __shfl_xor_sync(0xffffffffu, t0, 2);
        t0 += __shfl_xor_sync(0xffffffffu, t0, 4);
        float l0 = t0 * SC;
        float nm = fmaxf(m, l0);
        float fac = __expf(m - nm);
        float e0 = __expf(l0 - nm);
        s = s * fac + e0;
        acc.x = acc.x * fac + v0.x * e0;
        acc.y = acc.y * fac + v0.y * e0;
        acc.z = acc.z * fac + v0.z * e0;
        acc.w = acc.w * fac + v0.w * e0;
        m = nm;
    }

    float inv = 1.f / (s + 1e-16f);
    const float4 sk = *(const float4*)(g_skip + node * DD + lane * 4);
    float4 o;
    o.x = acc.x * inv + sk.x;
    o.y = acc.y * inv + sk.y;
    o.z = acc.z * inv + sk.z;
    o.w = acc.w * inv + sk.w;
    if (do_relu) {
        o.x = fmaxf(o.x, 0.f);
        o.y = fmaxf(o.y, 0.f);
        o.z = fmaxf(o.z, 0.f);
        o.w = fmaxf(o.w, 0.f);
    }
    *(float4*)(out + node * DD + lane * 4) = o;
}

// ---------------- launch ----------------------------------------------------
extern "C" void kernel_launch(void* const* d_in, const int* in_sizes, int n_in,
                              void* d_out, int out_size) {
    const float* x = (const float*)d_in[0];
    const void* ei = d_in[1];    // int32 or int64 — detected on device
    float* out = (float*)d_out;

    const int NB_SCAN1 = (NN + 511) / 512;       // 98
    const dim3 PROJ_GRID((NN + 63) / 64, 4);     // 782 x 4 matrices
    const int ATTN_GRID = (NN + 7) / 8;          // 6250

    k_detect_zero<<<(NN + 255) / 256, 256>>>((const int*)ei);      // 0
    k_wrepack<<<512, 256>>>(                                       // 1
        (const float*)d_in[2], (const float*)d_in[4],
        (const float*)d_in[6], (const float*)d_in[8],
        (const float*)d_in[10], (const float*)d_in[12],
        (const float*)d_in[14], (const float*)d_in[16]);
    k_hist<<<(EE + 255) / 256, 256>>>(ei);                         // 2
    k_proj<<<PROJ_GRID, 128>>>(x, 0,                               // 3 (profiled)
        (const float*)d_in[3], (const float*)d_in[5],
        (const float*)d_in[7], (const float*)d_in[9]);
    k_scan1<<<NB_SCAN1, 512>>>();                                  // 4
    k_scan2<<<1, 128>>>(NB_SCAN1);                                 // 5
    k_scan3<<<(NN + 255) / 256, 256>>>();                          // 6
    k_scatter<<<(EE + 255) / 256, 256>>>(ei);                      // 7
    k_attn<<<ATTN_GRID, 256>>>(nullptr);                           // 8: g_h + relu
    k_proj<<<PROJ_GRID, 128>>>(nullptr, 4,                         // 9
        (const float*)d_in[11], (const float*)d_in[13],
        (const float*)d_in[15], (const float*)d_in[17]);
    k_attn<<<ATTN_GRID, 256>>>(out);                               // 10
}

// round 14
// speedup vs baseline: 1.4223x; 1.0425x over previous
#include <cuda_runtime.h>
#include <cstdint>

#define NN 50000
#define EE 800000
#define DD 128

// ---------------- scratch (static device globals; no allocation allowed) ----
__device__ __align__(16) float g_q[NN * DD];
__device__ __align__(16) float g_k[NN * DD];
__device__ __align__(16) float g_v[NN * DD];
__device__ __align__(16) float g_skip[NN * DD];
__device__ __align__(16) float g_h[NN * DD];

// tf32 weights, REPACKED into per-thread mma fragment order (see k_wrepack)
__device__ __align__(16) unsigned g_wt[8 * DD * DD];

__device__ __align__(16) int g_deg[NN];
__device__ __align__(16) int g_off[NN + 2];
__device__ __align__(16) int g_cursor[NN];
__device__ __align__(16) int g_bsum[128];
__device__ __align__(16) int g_boff[128];
__device__ __align__(16) int g_csrc[EE];
__device__ int g_is64;

// ---------------- fused: zero degree array + edge dtype detection -----------
__global__ void k_detect_zero(const int* __restrict__ p) {
    int i = blockIdx.x * blockDim.x + threadIdx.x;
    if (i < NN) g_deg[i] = 0;
    if (blockIdx.x == 0) {
        __shared__ int any;
        if (threadIdx.x == 0) any = 0;
        __syncthreads();
        int nz = 0;
        for (int t = threadIdx.x; t < 1024; t += blockDim.x) nz |= p[2 * t + 1];
        if (nz) any = 1;
        __syncthreads();
        if (threadIdx.x == 0) g_is64 = (any == 0);
    }
}

__device__ __forceinline__ int load_edge(const void* ei, long long idx) {
    int v;
    if (g_is64) v = (int)((const long long*)ei)[idx];
    else        v = ((const int*)ei)[idx];
    return min(max(v, 0), NN - 1);
}

// ---------------- weight conversion + fragment repack ------------------------
// Packed word index within one matrix: t = ((k0g*8 + j)*32 + lane)*4 + c
//   j<4:  b0 for nf = j*4 + c      -> W[k0g*8 + tig][ (j*4+c)*8 + gid ]
//   j>=4: b1 for nf = (j-4)*4 + c  -> W[k0g*8 + tig + 4][ ((j-4)*4+c)*8 + gid ]
__global__ void k_wrepack(
    const float* __restrict__ w0, const float* __restrict__ w1,
    const float* __restrict__ w2, const float* __restrict__ w3,
    const float* __restrict__ w4, const float* __restrict__ w5,
    const float* __restrict__ w6, const float* __restrict__ w7)
{
    int i = blockIdx.x * blockDim.x + threadIdx.x;     // 0 .. 131071
    int m = i >> 14;
    int t = i & 16383;
    int c = t & 3;
    int lane = (t >> 2) & 31;
    int j = (t >> 7) & 7;
    int k0g = t >> 10;
    int gid = lane >> 2, tig = lane & 3;
    int nf = (j & 3) * 4 + c;
    int k = k0g * 8 + tig + ((j >= 4) ? 4 : 0);
    int n = nf * 8 + gid;
    const float* src =
        (m == 0) ? w0 : (m == 1) ? w1 : (m == 2) ? w2 : (m == 3) ? w3 :
        (m == 4) ? w4 : (m == 5) ? w5 : (m == 6) ? w6 : w7;
    float f = src[k * DD + n];
    unsigned u;
    asm("cvt.rna.tf32.f32 %0, %1;" : "=r"(u) : "f"(f));
    g_wt[i] = u;
}

// ---------------- CSR build -------------------------------------------------
__global__ void k_hist(const void* __restrict__ ei) {
    int e = blockIdx.x * blockDim.x + threadIdx.x;
    if (e < EE) atomicAdd(&g_deg[load_edge(ei, (long long)EE + e)], 1);
}

__global__ void k_scan1() {
    __shared__ int sh[512];
    int tid = threadIdx.x;
    int i = blockIdx.x * 512 + tid;
    int v = (i < NN) ? g_deg[i] : 0;
    sh[tid] = v;
    __syncthreads();
    for (int off = 1; off < 512; off <<= 1) {
        int t = 0;
        if (tid >= off) t = sh[tid - off];
        __syncthreads();
        sh[tid] += t;
        __syncthreads();
    }
    if (i < NN) g_off[i] = sh[tid] - v;
    if (tid == 511) g_bsum[blockIdx.x] = sh[511];
}

__global__ void k_scan2(int nb) {
    __shared__ int sh[128];
    int tid = threadIdx.x;
    int v = (tid < nb) ? g_bsum[tid] : 0;
    sh[tid] = v;
    __syncthreads();
    for (int off = 1; off < 128; off <<= 1) {
        int t = 0;
        if (tid >= off) t = sh[tid - off];
        __syncthreads();
        sh[tid] += t;
        __syncthreads();
    }
    g_boff[tid] = sh[tid] - v;
}

__global__ void k_scan3() {
    int i = blockIdx.x * blockDim.x + threadIdx.x;
    if (i < NN) {
        int o = g_off[i] + g_boff[i >> 9];
        g_off[i] = o;
        g_cursor[i] = o;
    }
    if (i == 0) g_off[NN] = EE;
}

__global__ void k_scatter(const void* __restrict__ ei) {
    int e = blockIdx.x * blockDim.x + threadIdx.x;
    if (e < EE) {
        int dst = load_edge(ei, (long long)EE + e);
        int src = load_edge(ei, e);
        int pos = atomicAdd(&g_cursor[dst], 1);
        if (pos < EE) g_csrc[pos] = src;
    }
}

// ---------------- tensor-core projection GEMM (tf32 mma.sync) ---------------
// Grid (782, 4): block = one matrix x one 64-row tile. NEW: N-SPLIT across
// warps — warp w owns output cols [32w, 32w+32) for ALL 64 rows. Weight
// fetch per k-group drops 8 -> 2 LDG.128 per warp (4x less L1 traffic);
// A-frags come from smem (conflict-free: bank = (4*gid+tig)%32 covers all).
// mma count & acc regs unchanged.
__global__ void __launch_bounds__(128, 4) k_proj(
    const float* __restrict__ x_in, int wbase,
    const float* __restrict__ bq, const float* __restrict__ bk,
    const float* __restrict__ bv, const float* __restrict__ bs)
{
    __shared__ unsigned xs[64 * 132];          // tf32 bits, padded stride

    const float* x = (x_in != nullptr) ? x_in : g_h;
    int tid = threadIdx.x;
    int row0 = blockIdx.x * 64;
    int m = blockIdx.y;

    for (int i = tid; i < 64 * 32; i += 128) { // 32 float4 per row
        int r = i >> 5, c = (i & 31) * 4;
        float4 v = make_float4(0.f, 0.f, 0.f, 0.f);
        int row = row0 + r;
        if (row < NN) v = *(const float4*)(x + row * DD + c);
        unsigned u0, u1, u2, u3;
        asm("cvt.rna.tf32.f32 %0, %1;" : "=r"(u0) : "f"(v.x));
        asm("cvt.rna.tf32.f32 %0, %1;" : "=r"(u1) : "f"(v.y));
        asm("cvt.rna.tf32.f32 %0, %1;" : "=r"(u2) : "f"(v.z));
        asm("cvt.rna.tf32.f32 %0, %1;" : "=r"(u3) : "f"(v.w));
        *(uint4*)(&xs[r * 132 + c]) = make_uint4(u0, u1, u2, u3);
    }
    __syncthreads();

    int warp = tid >> 5, lane = tid & 31;
    int gid = lane >> 2, tig = lane & 3;

    const uint4* Wp = (const uint4*)(g_wt + (wbase + m) * (DD * DD));
    const float* B = (m == 0) ? bq : (m == 1) ? bk : (m == 2) ? bv : bs;
    float* O = (m == 0) ? g_q : (m == 1) ? g_k : (m == 2) ? g_v : g_skip;

    // acc[mg][c][4]: m-group mg (rows mg*16+gid, +8), col-frag nf = warp*4+c
    float acc[4][4][4];
#pragma unroll
    for (int c = 0; c < 4; c++) {
        float2 bb = *(const float2*)(B + (warp * 4 + c) * 8 + 2 * tig);
#pragma unroll
        for (int mg = 0; mg < 4; mg++) {
            acc[mg][c][0] = bb.x; acc[mg][c][1] = bb.y;
            acc[mg][c][2] = bb.x; acc[mg][c][3] = bb.y;
        }
    }

#pragma unroll
    for (int k0g = 0; k0g < 16; k0g++) {
        uint4 ulo = Wp[(k0g * 8 + warp) * 32 + lane];        // b0 frags
        uint4 uhi = Wp[(k0g * 8 + 4 + warp) * 32 + lane];    // b1 frags

        int k0 = k0g * 8;
        unsigned a[4][4];
#pragma unroll
        for (int mg = 0; mg < 4; mg++) {
            int r = mg * 16 + gid;
            a[mg][0] = xs[r * 132 + k0 + tig];
            a[mg][1] = xs[(r + 8) * 132 + k0 + tig];
            a[mg][2] = xs[r * 132 + k0 + tig + 4];
            a[mg][3] = xs[(r + 8) * 132 + k0 + tig + 4];
        }

#pragma unroll
        for (int mg = 0; mg < 4; mg++) {
#pragma unroll
            for (int c = 0; c < 4; c++) {
                unsigned b0 = (c == 0) ? ulo.x : (c == 1) ? ulo.y
                            : (c == 2) ? ulo.z : ulo.w;
                unsigned b1 = (c == 0) ? uhi.x : (c == 1) ? uhi.y
                            : (c == 2) ? uhi.z : uhi.w;
                asm volatile(
                    "mma.sync.aligned.m16n8k8.row.col.f32.tf32.tf32.f32 "
                    "{%0,%1,%2,%3}, {%4,%5,%6,%7}, {%8,%9}, {%0,%1,%2,%3};\n"
                    : "+f"(acc[mg][c][0]), "+f"(acc[mg][c][1]),
                      "+f"(acc[mg][c][2]), "+f"(acc[mg][c][3])
                    : "r"(a[mg][0]), "r"(a[mg][1]), "r"(a[mg][2]), "r"(a[mg][3]),
                      "r"(b0), "r"(b1));
            }
        }
    }

#pragma unroll
    for (int mg = 0; mg < 4; mg++) {
        int rg = row0 + mg * 16 + gid;
#pragma unroll
        for (int c = 0; c < 4; c++) {
            int col = (warp * 4 + c) * 8 + 2 * tig;
            if (rg < NN)
                *(float2*)(O + rg * DD + col) =
                    make_float2(acc[mg][c][0], acc[mg][c][1]);
            if (rg + 8 < NN)
                *(float2*)(O + (rg + 8) * DD + col) =
                    make_float2(acc[mg][c][2], acc[mg][c][3]);
        }
    }
}

// ---------------- warp-per-node online-softmax attention + skip ------------
// 2 edges per iteration (round-7 best variant).
__global__ void __launch_bounds__(256) k_attn(float* out_ptr) {
    int node = (blockIdx.x * blockDim.x + threadIdx.x) >> 5;
    if (node >= NN) return;
    int lane = threadIdx.x & 31;

    int do_relu = (out_ptr == nullptr);
    float* out = do_relu ? g_h : out_ptr;

    const float4 q4 = *(const float4*)(g_q + node * DD + lane * 4);

    float4 acc = make_float4(0.f, 0.f, 0.f, 0.f);
    float m = -1e30f, s = 0.f;

    int j = g_off[node];
    int end = g_off[node + 1];
    const float SC = 0.17677669529663689f;       // 1/sqrt(32)

    for (; j + 2 <= end; j += 2) {
        int s0 = g_csrc[j];
        int s1 = g_csrc[j + 1];
        const float4 k0 = *(const float4*)(g_k + s0 * DD + lane * 4);
        const float4 v0 = *(const float4*)(g_v + s0 * DD + lane * 4);
        const float4 k1 = *(const float4*)(g_k + s1 * DD + lane * 4);
        const float4 v1 = *(const float4*)(g_v + s1 * DD + lane * 4);

        float t0 = q4.x * k0.x + q4.y * k0.y + q4.z * k0.z + q4.w * k0.w;
        float t1 = q4.x * k1.x + q4.y * k1.y + q4.z * k1.z + q4.w * k1.w;
        t0 += __shfl_xor_sync(0xffffffffu, t0, 1);
        t1 += __shfl_xor_sync(0xffffffffu, t1, 1);
        t0 += __shfl_xor_sync(0xffffffffu, t0, 2);
        t1 += __shfl_xor_sync(0xffffffffu, t1, 2);
        t0 += __shfl_xor_sync(0xffffffffu, t0, 4);
        t1 += __shfl_xor_sync(0xffffffffu, t1, 4);

        float l0 = t0 * SC;
        float l1 = t1 * SC;
        float nm = fmaxf(m, fmaxf(l0, l1));
        float fac = __expf(m - nm);
        float e0 = __expf(l0 - nm);
        float e1 = __expf(l1 - nm);
        s = s * fac + e0 + e1;
        acc.x = acc.x * fac + v0.x * e0 + v1.x * e1;
        acc.y = acc.y * fac + v0.y * e0 + v1.y * e1;
        acc.z = acc.z * fac + v0.z * e0 + v1.z * e1;
        acc.w = acc.w * fac + v0.w * e0 + v1.w * e1;
        m = nm;
    }
    if (j < end) {
        int s0 = g_csrc[j];
        const float4 k0 = *(const float4*)(g_k + s0 * DD + lane * 4);
        const float4 v0 = *(const float4*)(g_v + s0 * DD + lane * 4);
        float t0 = q4.x * k0.x + q4.y * k0.y + q4.z * k0.z + q4.w * k0.w;
        t0 += __shfl_xor_sync(0xffffffffu, t0, 1);
        t0 += __shfl_xor_sync(0xffffffffu, t0, 2);
        t0 += __shfl_xor_sync(0xffffffffu, t0, 4);
        float l0 = t0 * SC;
        float nm = fmaxf(m, l0);
        float fac = __expf(m - nm);
        float e0 = __expf(l0 - nm);
        s = s * fac + e0;
        acc.x = acc.x * fac + v0.x * e0;
        acc.y = acc.y * fac + v0.y * e0;
        acc.z = acc.z * fac + v0.z * e0;
        acc.w = acc.w * fac + v0.w * e0;
        m = nm;
    }

    float inv = 1.f / (s + 1e-16f);
    const float4 sk = *(const float4*)(g_skip + node * DD + lane * 4);
    float4 o;
    o.x = acc.x * inv + sk.x;
    o.y = acc.y * inv + sk.y;
    o.z = acc.z * inv + sk.z;
    o.w = acc.w * inv + sk.w;
    if (do_relu) {
        o.x = fmaxf(o.x, 0.f);
        o.y = fmaxf(o.y, 0.f);
        o.z = fmaxf(o.z, 0.f);
        o.w = fmaxf(o.w, 0.f);
    }
    *(float4*)(out + node * DD + lane * 4) = o;
}

// ---------------- launch ----------------------------------------------------
extern "C" void kernel_launch(void* const* d_in, const int* in_sizes, int n_in,
                              void* d_out, int out_size) {
    const float* x = (const float*)d_in[0];
    const void* ei = d_in[1];    // int32 or int64 — detected on device
    float* out = (float*)d_out;

    const int NB_SCAN1 = (NN + 511) / 512;       // 98
    const dim3 PROJ_GRID((NN + 63) / 64, 4);     // 782 x 4 matrices
    const int ATTN_GRID = (NN + 7) / 8;          // 6250

    k_detect_zero<<<(NN + 255) / 256, 256>>>((const int*)ei);      // 0
    k_wrepack<<<512, 256>>>(                                       // 1
        (const float*)d_in[2], (const float*)d_in[4],
        (const float*)d_in[6], (const float*)d_in[8],
        (const float*)d_in[10], (const float*)d_in[12],
        (const float*)d_in[14], (const float*)d_in[16]);
    k_hist<<<(EE + 255) / 256, 256>>>(ei);                         // 2
    k_proj<<<PROJ_GRID, 128>>>(x, 0,                               // 3 (profiled)
        (const float*)d_in[3], (const float*)d_in[5],
        (const float*)d_in[7], (const float*)d_in[9]);
    k_scan1<<<NB_SCAN1, 512>>>();                                  // 4
    k_scan2<<<1, 128>>>(NB_SCAN1);                                 // 5
    k_scan3<<<(NN + 255) / 256, 256>>>();                          // 6
    k_scatter<<<(EE + 255) / 256, 256>>>(ei);                      // 7
    k_attn<<<ATTN_GRID, 256>>>(nullptr);                           // 8: g_h + relu
    k_proj<<<PROJ_GRID, 128>>>(nullptr, 4,                         // 9
        (const float*)d_in[11], (const float*)d_in[13],
        (const float*)d_in[15], (const float*)d_in[17]);
    k_attn<<<ATTN_GRID, 256>>>(out);                               // 10
}

// round 15
// speedup vs baseline: 1.4892x; 1.0470x over previous
#include <cuda_runtime.h>
#include <cstdint>

#define NN 50000
#define EE 800000
#define DD 128

// ---------------- scratch (static device globals; no allocation allowed) ----
__device__ __align__(16) float g_q[NN * DD];
__device__ __align__(16) float g_k[NN * DD];
__device__ __align__(16) float g_v[NN * DD];
__device__ __align__(16) float g_skip[NN * DD];
__device__ __align__(16) float g_h[NN * DD];

// tf32 weights, REPACKED into per-thread mma fragment order (see k_wrepack)
__device__ __align__(16) unsigned g_wt[8 * DD * DD];

__device__ __align__(16) int g_deg[NN];
__device__ __align__(16) int g_off[NN + 2];
__device__ __align__(16) int g_cursor[NN];
__device__ __align__(16) int g_bsum[128];
__device__ __align__(16) int g_boff[128];
__device__ __align__(16) int g_csrc[EE];
__device__ int g_is64;

// ---------------- fused: zero degree array + edge dtype detection -----------
__global__ void k_detect_zero(const int* __restrict__ p) {
    int i = blockIdx.x * blockDim.x + threadIdx.x;
    if (i < NN) g_deg[i] = 0;
    if (blockIdx.x == 0) {
        __shared__ int any;
        if (threadIdx.x == 0) any = 0;
        __syncthreads();
        int nz = 0;
        for (int t = threadIdx.x; t < 1024; t += blockDim.x) nz |= p[2 * t + 1];
        if (nz) any = 1;
        __syncthreads();
        if (threadIdx.x == 0) g_is64 = (any == 0);
    }
}

__device__ __forceinline__ int load_edge(const void* ei, long long idx) {
    int v;
    if (g_is64) v = (int)((const long long*)ei)[idx];
    else        v = ((const int*)ei)[idx];
    return min(max(v, 0), NN - 1);
}

// ---------------- weight conversion + fragment repack ------------------------
// Packed word index within one matrix: t = ((k0g*8 + j)*32 + lane)*4 + c
//   j<4:  b0 for nf = j*4 + c      -> W[k0g*8 + tig][ (j*4+c)*8 + gid ]
//   j>=4: b1 for nf = (j-4)*4 + c  -> W[k0g*8 + tig + 4][ ((j-4)*4+c)*8 + gid ]
__global__ void k_wrepack(
    const float* __restrict__ w0, const float* __restrict__ w1,
    const float* __restrict__ w2, const float* __restrict__ w3,
    const float* __restrict__ w4, const float* __restrict__ w5,
    const float* __restrict__ w6, const float* __restrict__ w7)
{
    int i = blockIdx.x * blockDim.x + threadIdx.x;     // 0 .. 131071
    int m = i >> 14;
    int t = i & 16383;
    int c = t & 3;
    int lane = (t >> 2) & 31;
    int j = (t >> 7) & 7;
    int k0g = t >> 10;
    int gid = lane >> 2, tig = lane & 3;
    int nf = (j & 3) * 4 + c;
    int k = k0g * 8 + tig + ((j >= 4) ? 4 : 0);
    int n = nf * 8 + gid;
    const float* src =
        (m == 0) ? w0 : (m == 1) ? w1 : (m == 2) ? w2 : (m == 3) ? w3 :
        (m == 4) ? w4 : (m == 5) ? w5 : (m == 6) ? w6 : w7;
    float f = src[k * DD + n];
    unsigned u;
    asm("cvt.rna.tf32.f32 %0, %1;" : "=r"(u) : "f"(f));
    g_wt[i] = u;
}

// ---------------- CSR build -------------------------------------------------
__global__ void k_hist(const void* __restrict__ ei) {
    int e = blockIdx.x * blockDim.x + threadIdx.x;
    if (e < EE) atomicAdd(&g_deg[load_edge(ei, (long long)EE + e)], 1);
}

__global__ void k_scan1() {
    __shared__ int sh[512];
    int tid = threadIdx.x;
    int i = blockIdx.x * 512 + tid;
    int v = (i < NN) ? g_deg[i] : 0;
    sh[tid] = v;
    __syncthreads();
    for (int off = 1; off < 512; off <<= 1) {
        int t = 0;
        if (tid >= off) t = sh[tid - off];
        __syncthreads();
        sh[tid] += t;
        __syncthreads();
    }
    if (i < NN) g_off[i] = sh[tid] - v;
    if (tid == 511) g_bsum[blockIdx.x] = sh[511];
}

__global__ void k_scan2(int nb) {
    __shared__ int sh[128];
    int tid = threadIdx.x;
    int v = (tid < nb) ? g_bsum[tid] : 0;
    sh[tid] = v;
    __syncthreads();
    for (int off = 1; off < 128; off <<= 1) {
        int t = 0;
        if (tid >= off) t = sh[tid - off];
        __syncthreads();
        sh[tid] += t;
        __syncthreads();
    }
    g_boff[tid] = sh[tid] - v;
}

__global__ void k_scan3() {
    int i = blockIdx.x * blockDim.x + threadIdx.x;
    if (i < NN) {
        int o = g_off[i] + g_boff[i >> 9];
        g_off[i] = o;
        g_cursor[i] = o;
    }
    if (i == 0) g_off[NN] = EE;
}

__global__ void k_scatter(const void* __restrict__ ei) {
    int e = blockIdx.x * blockDim.x + threadIdx.x;
    if (e < EE) {
        int dst = load_edge(ei, (long long)EE + e);
        int src = load_edge(ei, e);
        int pos = atomicAdd(&g_cursor[dst], 1);
        if (pos < EE) g_csrc[pos] = src;
    }
}

// ---------------- tensor-core projection GEMM (tf32 mma.sync) ---------------
// Grid (782, 4): block = one matrix x one 64-row tile. N-SPLIT across warps:
// warp w owns output cols [32w, 32w+32) for all 64 rows. 2x LDG.128 weight
// fetch per k-group per warp; A-frags from conflict-free smem.
__global__ void __launch_bounds__(128, 4) k_proj(
    const float* __restrict__ x_in, int wbase,
    const float* __restrict__ bq, const float* __restrict__ bk,
    const float* __restrict__ bv, const float* __restrict__ bs)
{
    __shared__ unsigned xs[64 * 132];          // tf32 bits, padded stride

    const float* x = (x_in != nullptr) ? x_in : g_h;
    int tid = threadIdx.x;
    int row0 = blockIdx.x * 64;
    int m = blockIdx.y;

    for (int i = tid; i < 64 * 32; i += 128) { // 32 float4 per row
        int r = i >> 5, c = (i & 31) * 4;
        float4 v = make_float4(0.f, 0.f, 0.f, 0.f);
        int row = row0 + r;
        if (row < NN) v = *(const float4*)(x + row * DD + c);
        unsigned u0, u1, u2, u3;
        asm("cvt.rna.tf32.f32 %0, %1;" : "=r"(u0) : "f"(v.x));
        asm("cvt.rna.tf32.f32 %0, %1;" : "=r"(u1) : "f"(v.y));
        asm("cvt.rna.tf32.f32 %0, %1;" : "=r"(u2) : "f"(v.z));
        asm("cvt.rna.tf32.f32 %0, %1;" : "=r"(u3) : "f"(v.w));
        *(uint4*)(&xs[r * 132 + c]) = make_uint4(u0, u1, u2, u3);
    }
    __syncthreads();

    int warp = tid >> 5, lane = tid & 31;
    int gid = lane >> 2, tig = lane & 3;

    const uint4* Wp = (const uint4*)(g_wt + (wbase + m) * (DD * DD));
    const float* B = (m == 0) ? bq : (m == 1) ? bk : (m == 2) ? bv : bs;
    float* O = (m == 0) ? g_q : (m == 1) ? g_k : (m == 2) ? g_v : g_skip;

    // acc[mg][c][4]: m-group mg (rows mg*16+gid, +8), col-frag nf = warp*4+c
    float acc[4][4][4];
#pragma unroll
    for (int c = 0; c < 4; c++) {
        float2 bb = *(const float2*)(B + (warp * 4 + c) * 8 + 2 * tig);
#pragma unroll
        for (int mg = 0; mg < 4; mg++) {
            acc[mg][c][0] = bb.x; acc[mg][c][1] = bb.y;
            acc[mg][c][2] = bb.x; acc[mg][c][3] = bb.y;
        }
    }

#pragma unroll
    for (int k0g = 0; k0g < 16; k0g++) {
        uint4 ulo = Wp[(k0g * 8 + warp) * 32 + lane];        // b0 frags
        uint4 uhi = Wp[(k0g * 8 + 4 + warp) * 32 + lane];    // b1 frags

        int k0 = k0g * 8;
        unsigned a[4][4];
#pragma unroll
        for (int mg = 0; mg < 4; mg++) {
            int r = mg * 16 + gid;
            a[mg][0] = xs[r * 132 + k0 + tig];
            a[mg][1] = xs[(r + 8) * 132 + k0 + tig];
            a[mg][2] = xs[r * 132 + k0 + tig + 4];
            a[mg][3] = xs[(r + 8) * 132 + k0 + tig + 4];
        }

#pragma unroll
        for (int mg = 0; mg < 4; mg++) {
#pragma unroll
            for (int c = 0; c < 4; c++) {
                unsigned b0 = (c == 0) ? ulo.x : (c == 1) ? ulo.y
                            : (c == 2) ? ulo.z : ulo.w;
                unsigned b1 = (c == 0) ? uhi.x : (c == 1) ? uhi.y
                            : (c == 2) ? uhi.z : uhi.w;
                asm volatile(
                    "mma.sync.aligned.m16n8k8.row.col.f32.tf32.tf32.f32 "
                    "{%0,%1,%2,%3}, {%4,%5,%6,%7}, {%8,%9}, {%0,%1,%2,%3};\n"
                    : "+f"(acc[mg][c][0]), "+f"(acc[mg][c][1]),
                      "+f"(acc[mg][c][2]), "+f"(acc[mg][c][3])
                    : "r"(a[mg][0]), "r"(a[mg][1]), "r"(a[mg][2]), "r"(a[mg][3]),
                      "r"(b0), "r"(b1));
            }
        }
    }

#pragma unroll
    for (int mg = 0; mg < 4; mg++) {
        int rg = row0 + mg * 16 + gid;
#pragma unroll
        for (int c = 0; c < 4; c++) {
            int col = (warp * 4 + c) * 8 + 2 * tig;
            if (rg < NN)
                *(float2*)(O + rg * DD + col) =
                    make_float2(acc[mg][c][0], acc[mg][c][1]);
            if (rg + 8 < NN)
                *(float2*)(O + (rg + 8) * DD + col) =
                    make_float2(acc[mg][c][2], acc[mg][c][3]);
        }
    }
}

// ---------------- warp-per-node online-softmax attention + skip ------------
// 2 edges per iteration (round-7 best variant).
__global__ void __launch_bounds__(256) k_attn(float* out_ptr) {
    int node = (blockIdx.x * blockDim.x + threadIdx.x) >> 5;
    if (node >= NN) return;
    int lane = threadIdx.x & 31;

    int do_relu = (out_ptr == nullptr);
    float* out = do_relu ? g_h : out_ptr;

    const float4 q4 = *(const float4*)(g_q + node * DD + lane * 4);

    float4 acc = make_float4(0.f, 0.f, 0.f, 0.f);
    float m = -1e30f, s = 0.f;

    int j = g_off[node];
    int end = g_off[node + 1];
    const float SC = 0.17677669529663689f;       // 1/sqrt(32)

    for (; j + 2 <= end; j += 2) {
        int s0 = g_csrc[j];
        int s1 = g_csrc[j + 1];
        const float4 k0 = *(const float4*)(g_k + s0 * DD + lane * 4);
        const float4 v0 = *(const float4*)(g_v + s0 * DD + lane * 4);
        const float4 k1 = *(const float4*)(g_k + s1 * DD + lane * 4);
        const float4 v1 = *(const float4*)(g_v + s1 * DD + lane * 4);

        float t0 = q4.x * k0.x + q4.y * k0.y + q4.z * k0.z + q4.w * k0.w;
        float t1 = q4.x * k1.x + q4.y * k1.y + q4.z * k1.z + q4.w * k1.w;
        t0 += __shfl_xor_sync(0xffffffffu, t0, 1);
        t1 += __shfl_xor_sync(0xffffffffu, t1, 1);
        t0 += __shfl_xor_sync(0xffffffffu, t0, 2);
        t1 += __shfl_xor_sync(0xffffffffu, t1, 2);
        t0 += __shfl_xor_sync(0xffffffffu, t0, 4);
        t1 += __shfl_xor_sync(0xffffffffu, t1, 4);

        float l0 = t0 * SC;
        float l1 = t1 * SC;
        float nm = fmaxf(m, fmaxf(l0, l1));
        float fac = __expf(m - nm);
        float e0 = __expf(l0 - nm);
        float e1 = __expf(l1 - nm);
        s = s * fac + e0 + e1;
        acc.x = acc.x * fac + v0.x * e0 + v1.x * e1;
        acc.y = acc.y * fac + v0.y * e0 + v1.y * e1;
        acc.z = acc.z * fac + v0.z * e0 + v1.z * e1;
        acc.w = acc.w * fac + v0.w * e0 + v1.w * e1;
        m = nm;
    }
    if (j < end) {
        int s0 = g_csrc[j];
        const float4 k0 = *(const float4*)(g_k + s0 * DD + lane * 4);
        const float4 v0 = *(const float4*)(g_v + s0 * DD + lane * 4);
        float t0 = q4.x * k0.x + q4.y * k0.y + q4.z * k0.z + q4.w * k0.w;
        t0 += __shfl_xor_sync(0xffffffffu, t0, 1);
        t0 += __shfl_xor_sync(0xffffffffu, t0, 2);
        t0 += __shfl_xor_sync(0xffffffffu, t0, 4);
        float l0 = t0 * SC;
        float nm = fmaxf(m, l0);
        float fac = __expf(m - nm);
        float e0 = __expf(l0 - nm);
        s = s * fac + e0;
        acc.x = acc.x * fac + v0.x * e0;
        acc.y = acc.y * fac + v0.y * e0;
        acc.z = acc.z * fac + v0.z * e0;
        acc.w = acc.w * fac + v0.w * e0;
        m = nm;
    }

    float inv = 1.f / (s + 1e-16f);
    const float4 sk = *(const float4*)(g_skip + node * DD + lane * 4);
    float4 o;
    o.x = acc.x * inv + sk.x;
    o.y = acc.y * inv + sk.y;
    o.z = acc.z * inv + sk.z;
    o.w = acc.w * inv + sk.w;
    if (do_relu) {
        o.x = fmaxf(o.x, 0.f);
        o.y = fmaxf(o.y, 0.f);
        o.z = fmaxf(o.z, 0.f);
        o.w = fmaxf(o.w, 0.f);
    }
    *(float4*)(out + node * DD + lane * 4) = o;
}

// ---------------- launch ----------------------------------------------------
// Fork/join: CSR chain (hist->scan1->scan2->scan3->scatter) runs on a second
// non-blocking stream, concurrent with wrepack + proj L0 (data-disjoint).
// Join via event before attn L0. Streams/events created once (host objects,
// no device memory). All ops are graph-capturable.
extern "C" void kernel_launch(void* const* d_in, const int* in_sizes, int n_in,
                              void* d_out, int out_size) {
    const float* x = (const float*)d_in[0];
    const void* ei = d_in[1];    // int32 or int64 — detected on device
    float* out = (float*)d_out;

    static cudaStream_t s2 = nullptr;
    static cudaEvent_t ev0 = nullptr, ev1 = nullptr;
    if (s2 == nullptr) {
        cudaStreamCreateWithFlags(&s2, cudaStreamNonBlocking);
        cudaEventCreateWithFlags(&ev0, cudaEventDisableTiming);
        cudaEventCreateWithFlags(&ev1, cudaEventDisableTiming);
    }

    const int NB_SCAN1 = (NN + 511) / 512;       // 98
    const dim3 PROJ_GRID((NN + 63) / 64, 4);     // 782 x 4 matrices
    const int ATTN_GRID = (NN + 7) / 8;          // 6250

    // main stream: detect/zero, then weight chain
    k_detect_zero<<<(NN + 255) / 256, 256>>>((const int*)ei);          // 0
    cudaEventRecord(ev0, 0);
    cudaStreamWaitEvent(s2, ev0, 0);

    k_hist<<<(EE + 255) / 256, 256, 0, s2>>>(ei);                      // 1 (s2)
    k_wrepack<<<512, 256>>>(                                           // 2
        (const float*)d_in[2], (const float*)d_in[4],
        (const float*)d_in[6], (const float*)d_in[8],
        (const float*)d_in[10], (const float*)d_in[12],
        (const float*)d_in[14], (const float*)d_in[16]);
    k_proj<<<PROJ_GRID, 128>>>(x, 0,                                   // 3 (profiled)
        (const float*)d_in[3], (const float*)d_in[5],
        (const float*)d_in[7], (const float*)d_in[9]);

    k_scan1<<<NB_SCAN1, 512, 0, s2>>>();                               // 4 (s2)
    k_scan2<<<1, 128, 0, s2>>>(NB_SCAN1);                              // 5 (s2)
    k_scan3<<<(NN + 255) / 256, 256, 0, s2>>>();                       // 6 (s2)
    k_scatter<<<(EE + 255) / 256, 256, 0, s2>>>(ei);                   // 7 (s2)
    cudaEventRecord(ev1, s2);

    cudaStreamWaitEvent(0, ev1, 0);              // join: attn needs CSR + proj
    k_attn<<<ATTN_GRID, 256>>>(nullptr);                               // 8: g_h + relu
    k_proj<<<PROJ_GRID, 128>>>(nullptr, 4,                             // 9
        (const float*)d_in[11], (const float*)d_in[13],
        (const float*)d_in[15], (const float*)d_in[17]);
    k_attn<<<ATTN_GRID, 256>>>(out);                                   // 10
}

// round 17
// speedup vs baseline: 1.5651x; 1.0510x over previous
#include <cuda_runtime.h>
#include <cuda_fp16.h>
#include <cstdint>

#define NN 50000
#define EE 800000
#define DD 128

// ---------------- scratch (static device globals; no allocation allowed) ----
__device__ __align__(16) float g_q[NN * DD];
__device__ __align__(16) float g_skip[NN * DD];
__device__ __align__(16) float g_h[NN * DD];
__device__ __align__(16) __half g_k16[NN * DD];   // fp16 k (attention operand)
__device__ __align__(16) __half g_v16[NN * DD];   // fp16 v (attention operand)

// tf32 weights, REPACKED into per-thread mma fragment order (see k_wrepack)
__device__ __align__(16) unsigned g_wt[8 * DD * DD];

__device__ __align__(16) int g_deg[NN];
__device__ __align__(16) int g_off[NN + 2];
__device__ __align__(16) int g_cursor[NN];
__device__ __align__(16) int g_bsum[128];
__device__ __align__(16) int g_boff[128];
__device__ __align__(16) int g_csrc[EE];
__device__ int g_is64;

// ---------------- fused: zero degree array + edge dtype detection -----------
__global__ void k_detect_zero(const int* __restrict__ p) {
    int i = blockIdx.x * blockDim.x + threadIdx.x;
    if (i < NN) g_deg[i] = 0;
    if (blockIdx.x == 0) {
        __shared__ int any;
        if (threadIdx.x == 0) any = 0;
        __syncthreads();
        int nz = 0;
        for (int t = threadIdx.x; t < 1024; t += blockDim.x) nz |= p[2 * t + 1];
        if (nz) any = 1;
        __syncthreads();
        if (threadIdx.x == 0) g_is64 = (any == 0);
    }
}

__device__ __forceinline__ int load_edge(const void* ei, long long idx) {
    int v;
    if (g_is64) v = (int)((const long long*)ei)[idx];
    else        v = ((const int*)ei)[idx];
    return min(max(v, 0), NN - 1);
}

// ---------------- weight conversion + fragment repack ------------------------
__global__ void k_wrepack(
    const float* __restrict__ w0, const float* __restrict__ w1,
    const float* __restrict__ w2, const float* __restrict__ w3,
    const float* __restrict__ w4, const float* __restrict__ w5,
    const float* __restrict__ w6, const float* __restrict__ w7)
{
    int i = blockIdx.x * blockDim.x + threadIdx.x;     // 0 .. 131071
    int m = i >> 14;
    int t = i & 16383;
    int c = t & 3;
    int lane = (t >> 2) & 31;
    int j = (t >> 7) & 7;
    int k0g = t >> 10;
    int gid = lane >> 2, tig = lane & 3;
    int nf = (j & 3) * 4 + c;
    int k = k0g * 8 + tig + ((j >= 4) ? 4 : 0);
    int n = nf * 8 + gid;
    const float* src =
        (m == 0) ? w0 : (m == 1) ? w1 : (m == 2) ? w2 : (m == 3) ? w3 :
        (m == 4) ? w4 : (m == 5) ? w5 : (m == 6) ? w6 : w7;
    float f = src[k * DD + n];
    unsigned u;
    asm("cvt.rna.tf32.f32 %0, %1;" : "=r"(u) : "f"(f));
    g_wt[i] = u;
}

// ---------------- CSR build -------------------------------------------------
__global__ void k_hist(const void* __restrict__ ei) {
    int e = blockIdx.x * blockDim.x + threadIdx.x;
    if (e < EE) atomicAdd(&g_deg[load_edge(ei, (long long)EE + e)], 1);
}

__global__ void k_scan1() {
    __shared__ int sh[512];
    int tid = threadIdx.x;
    int i = blockIdx.x * 512 + tid;
    int v = (i < NN) ? g_deg[i] : 0;
    sh[tid] = v;
    __syncthreads();
    for (int off = 1; off < 512; off <<= 1) {
        int t = 0;
        if (tid >= off) t = sh[tid - off];
        __syncthreads();
        sh[tid] += t;
        __syncthreads();
    }
    if (i < NN) g_off[i] = sh[tid] - v;
    if (tid == 511) g_bsum[blockIdx.x] = sh[511];
}

__global__ void k_scan2(int nb) {
    __shared__ int sh[128];
    int tid = threadIdx.x;
    int v = (tid < nb) ? g_bsum[tid] : 0;
    sh[tid] = v;
    __syncthreads();
    for (int off = 1; off < 128; off <<= 1) {
        int t = 0;
        if (tid >= off) t = sh[tid - off];
        __syncthreads();
        sh[tid] += t;
        __syncthreads();
    }
    g_boff[tid] = sh[tid] - v;
}

__global__ void k_scan3() {
    int i = blockIdx.x * blockDim.x + threadIdx.x;
    if (i < NN) {
        int o = g_off[i] + g_boff[i >> 9];
        g_off[i] = o;
        g_cursor[i] = o;
    }
    if (i == 0) g_off[NN] = EE;
}

__global__ void k_scatter(const void* __restrict__ ei) {
    int e = blockIdx.x * blockDim.x + threadIdx.x;
    if (e < EE) {
        int dst = load_edge(ei, (long long)EE + e);
        int src = load_edge(ei, e);
        int pos = atomicAdd(&g_cursor[dst], 1);
        if (pos < EE) g_csrc[pos] = src;
    }
}

// ---------------- tensor-core projection GEMM (tf32 mma.sync) ---------------
// Grid (782, 4): block = one matrix x one 64-row tile. N-split across warps.
// Epilogue: m=0 -> g_q (fp32), m=3 -> g_skip (fp32), m=1/2 -> g_k16/g_v16
// (fp16 __half2 stores — halves attention gather traffic).
__global__ void __launch_bounds__(128, 4) k_proj(
    const float* __restrict__ x_in, int wbase,
    const float* __restrict__ bq, const float* __restrict__ bk,
    const float* __restrict__ bv, const float* __restrict__ bs)
{
    __shared__ unsigned xs[64 * 132];          // tf32 bits, padded stride

    const float* x = (x_in != nullptr) ? x_in : g_h;
    int tid = threadIdx.x;
    int row0 = blockIdx.x * 64;
    int m = blockIdx.y;

    for (int i = tid; i < 64 * 32; i += 128) { // 32 float4 per row
        int r = i >> 5, c = (i & 31) * 4;
        float4 v = make_float4(0.f, 0.f, 0.f, 0.f);
        int row = row0 + r;
        if (row < NN) v = *(const float4*)(x + row * DD + c);
        unsigned u0, u1, u2, u3;
        asm("cvt.rna.tf32.f32 %0, %1;" : "=r"(u0) : "f"(v.x));
        asm("cvt.rna.tf32.f32 %0, %1;" : "=r"(u1) : "f"(v.y));
        asm("cvt.rna.tf32.f32 %0, %1;" : "=r"(u2) : "f"(v.z));
        asm("cvt.rna.tf32.f32 %0, %1;" : "=r"(u3) : "f"(v.w));
        *(uint4*)(&xs[r * 132 + c]) = make_uint4(u0, u1, u2, u3);
    }
    __syncthreads();

    int warp = tid >> 5, lane = tid & 31;
    int gid = lane >> 2, tig = lane & 3;

    const uint4* Wp = (const uint4*)(g_wt + (wbase + m) * (DD * DD));
    const float* B = (m == 0) ? bq : (m == 1) ? bk : (m == 2) ? bv : bs;

    // acc[mg][c][4]: m-group mg (rows mg*16+gid, +8), col-frag nf = warp*4+c
    float acc[4][4][4];
#pragma unroll
    for (int c = 0; c < 4; c++) {
        float2 bb = *(const float2*)(B + (warp * 4 + c) * 8 + 2 * tig);
#pragma unroll
        for (int mg = 0; mg < 4; mg++) {
            acc[mg][c][0] = bb.x; acc[mg][c][1] = bb.y;
            acc[mg][c][2] = bb.x; acc[mg][c][3] = bb.y;
        }
    }

#pragma unroll
    for (int k0g = 0; k0g < 16; k0g++) {
        uint4 ulo = Wp[(k0g * 8 + warp) * 32 + lane];        // b0 frags
        uint4 uhi = Wp[(k0g * 8 + 4 + warp) * 32 + lane];    // b1 frags

        int k0 = k0g * 8;
        unsigned a[4][4];
#pragma unroll
        for (int mg = 0; mg < 4; mg++) {
            int r = mg * 16 + gid;
            a[mg][0] = xs[r * 132 + k0 + tig];
            a[mg][1] = xs[(r + 8) * 132 + k0 + tig];
            a[mg][2] = xs[r * 132 + k0 + tig + 4];
            a[mg][3] = xs[(r + 8) * 132 + k0 + tig + 4];
        }

#pragma unroll
        for (int mg = 0; mg < 4; mg++) {
#pragma unroll
            for (int c = 0; c < 4; c++) {
                unsigned b0 = (c == 0) ? ulo.x : (c == 1) ? ulo.y
                            : (c == 2) ? ulo.z : ulo.w;
                unsigned b1 = (c == 0) ? uhi.x : (c == 1) ? uhi.y
                            : (c == 2) ? uhi.z : uhi.w;
                asm volatile(
                    "mma.sync.aligned.m16n8k8.row.col.f32.tf32.tf32.f32 "
                    "{%0,%1,%2,%3}, {%4,%5,%6,%7}, {%8,%9}, {%0,%1,%2,%3};\n"
                    : "+f"(acc[mg][c][0]), "+f"(acc[mg][c][1]),
                      "+f"(acc[mg][c][2]), "+f"(acc[mg][c][3])
                    : "r"(a[mg][0]), "r"(a[mg][1]), "r"(a[mg][2]), "r"(a[mg][3]),
                      "r"(b0), "r"(b1));
            }
        }
    }

    if (m == 1 || m == 2) {
        __half* O16 = (m == 1) ? g_k16 : g_v16;
#pragma unroll
        for (int mg = 0; mg < 4; mg++) {
            int rg = row0 + mg * 16 + gid;
#pragma unroll
            for (int c = 0; c < 4; c++) {
                int col = (warp * 4 + c) * 8 + 2 * tig;
                if (rg < NN)
                    *(__half2*)(O16 + rg * DD + col) =
                        __floats2half2_rn(acc[mg][c][0], acc[mg][c][1]);
                if (rg + 8 < NN)
                    *(__half2*)(O16 + (rg + 8) * DD + col) =
                        __floats2half2_rn(acc[mg][c][2], acc[mg][c][3]);
            }
        }
    } else {
        float* O = (m == 0) ? g_q : g_skip;
#pragma unroll
        for (int mg = 0; mg < 4; mg++) {
            int rg = row0 + mg * 16 + gid;
#pragma unroll
            for (int c = 0; c < 4; c++) {
                int col = (warp * 4 + c) * 8 + 2 * tig;
                if (rg < NN)
                    *(float2*)(O + rg * DD + col) =
                        make_float2(acc[mg][c][0], acc[mg][c][1]);
                if (rg + 8 < NN)
                    *(float2*)(O + (rg + 8) * DD + col) =
                        make_float2(acc[mg][c][2], acc[mg][c][3]);
            }
        }
    }
}

// ---------------- warp-per-node online-softmax attention + skip ------------
// fp16 k/v gathers: 8B per lane per operand (256B/warp, coalesced), halving
// L2 traffic vs fp32. 2 edges per iteration.
__device__ __forceinline__ float4 ld_half4(const __half* p) {
    uint2 u = *(const uint2*)p;
    __half2 a = *reinterpret_cast<__half2*>(&u.x);
    __half2 b = *reinterpret_cast<__half2*>(&u.y);
    float2 fa = __half22float2(a), fb = __half22float2(b);
    return make_float4(fa.x, fa.y, fb.x, fb.y);
}

__global__ void __launch_bounds__(256) k_attn(float* out_ptr) {
    int node = (blockIdx.x * blockDim.x + threadIdx.x) >> 5;
    if (node >= NN) return;
    int lane = threadIdx.x & 31;

    int do_relu = (out_ptr == nullptr);
    float* out = do_relu ? g_h : out_ptr;

    const float4 q4 = *(const float4*)(g_q + node * DD + lane * 4);

    float4 acc = make_float4(0.f, 0.f, 0.f, 0.f);
    float m = -1e30f, s = 0.f;

    int j = g_off[node];
    int end = g_off[node + 1];
    const float SC = 0.17677669529663689f;       // 1/sqrt(32)

    for (; j + 2 <= end; j += 2) {
        int s0 = g_csrc[j];
        int s1 = g_csrc[j + 1];
        const float4 k0 = ld_half4(g_k16 + s0 * DD + lane * 4);
        const float4 v0 = ld_half4(g_v16 + s0 * DD + lane * 4);
        const float4 k1 = ld_half4(g_k16 + s1 * DD + lane * 4);
        const float4 v1 = ld_half4(g_v16 + s1 * DD + lane * 4);

        float t0 = q4.x * k0.x + q4.y * k0.y + q4.z * k0.z + q4.w * k0.w;
        float t1 = q4.x * k1.x + q4.y * k1.y + q4.z * k1.z + q4.w * k1.w;
        t0 += __shfl_xor_sync(0xffffffffu, t0, 1);
        t1 += __shfl_xor_sync(0xffffffffu, t1, 1);
        t0 += __shfl_xor_sync(0xffffffffu, t0, 2);
        t1 += __shfl_xor_sync(0xffffffffu, t1, 2);
        t0 += __shfl_xor_sync(0xffffffffu, t0, 4);
        t1 += __shfl_xor_sync(0xffffffffu, t1, 4);

        float l0 = t0 * SC;
        float l1 = t1 * SC;
        float nm = fmaxf(m, fmaxf(l0, l1));
        float fac = __expf(m - nm);
        float e0 = __expf(l0 - nm);
        float e1 = __expf(l1 - nm);
        s = s * fac + e0 + e1;
        acc.x = acc.x * fac + v0.x * e0 + v1.x * e1;
        acc.y = acc.y * fac + v0.y * e0 + v1.y * e1;
        acc.z = acc.z * fac + v0.z * e0 + v1.z * e1;
        acc.w = acc.w * fac + v0.w * e0 + v1.w * e1;
        m = nm;
    }
    if (j < end) {
        int s0 = g_csrc[j];
        const float4 k0 = ld_half4(g_k16 + s0 * DD + lane * 4);
        const float4 v0 = ld_half4(g_v16 + s0 * DD + lane * 4);
        float t0 = q4.x * k0.x + q4.y * k0.y + q4.z * k0.z + q4.w * k0.w;
        t0 += __shfl_xor_sync(0xffffffffu, t0, 1);
        t0 += __shfl_xor_sync(0xffffffffu, t0, 2);
        t0 += __shfl_xor_sync(0xffffffffu, t0, 4);
        float l0 = t0 * SC;
        float nm = fmaxf(m, l0);
        float fac = __expf(m - nm);
        float e0 = __expf(l0 - nm);
        s = s * fac + e0;
        acc.x = acc.x * fac + v0.x * e0;
        acc.y = acc.y * fac + v0.y * e0;
        acc.z = acc.z * fac + v0.z * e0;
        acc.w = acc.w * fac + v0.w * e0;
        m = nm;
    }

    float inv = 1.f / (s + 1e-16f);
    const float4 sk = *(const float4*)(g_skip + node * DD + lane * 4);
    float4 o;
    o.x = acc.x * inv + sk.x;
    o.y = acc.y * inv + sk.y;
    o.z = acc.z * inv + sk.z;
    o.w = acc.w * inv + sk.w;
    if (do_relu) {
        o.x = fmaxf(o.x, 0.f);
        o.y = fmaxf(o.y, 0.f);
        o.z = fmaxf(o.z, 0.f);
        o.w = fmaxf(o.w, 0.f);
    }
    *(float4*)(out + node * DD + lane * 4) = o;
}

// ---------------- launch ----------------------------------------------------
// Fork/join: CSR chain on a second non-blocking stream, concurrent with
// wrepack + proj L0 (data-disjoint). Join via event before attn L0.
extern "C" void kernel_launch(void* const* d_in, const int* in_sizes, int n_in,
                              void* d_out, int out_size) {
    const float* x = (const float*)d_in[0];
    const void* ei = d_in[1];    // int32 or int64 — detected on device
    float* out = (float*)d_out;

    static cudaStream_t s2 = nullptr;
    static cudaEvent_t ev0 = nullptr, ev1 = nullptr;
    if (s2 == nullptr) {
        cudaStreamCreateWithFlags(&s2, cudaStreamNonBlocking);
        cudaEventCreateWithFlags(&ev0, cudaEventDisableTiming);
        cudaEventCreateWithFlags(&ev1, cudaEventDisableTiming);
    }

    const int NB_SCAN1 = (NN + 511) / 512;       // 98
    const dim3 PROJ_GRID((NN + 63) / 64, 4);     // 782 x 4 matrices
    const int ATTN_GRID = (NN + 7) / 8;          // 6250

    // main stream: detect/zero, then weight chain
    k_detect_zero<<<(NN + 255) / 256, 256>>>((const int*)ei);          // 0
    cudaEventRecord(ev0, 0);
    cudaStreamWaitEvent(s2, ev0, 0);

    k_hist<<<(EE + 255) / 256, 256, 0, s2>>>(ei);                      // 1 (s2)
    k_wrepack<<<512, 256>>>(                                           // 2
        (const float*)d_in[2], (const float*)d_in[4],
        (const float*)d_in[6], (const float*)d_in[8],
        (const float*)d_in[10], (const float*)d_in[12],
        (const float*)d_in[14], (const float*)d_in[16]);
    k_proj<<<PROJ_GRID, 128>>>(x, 0,                                   // 3 (profiled)
        (const float*)d_in[3], (const float*)d_in[5],
        (const float*)d_in[7], (const float*)d_in[9]);

    k_scan1<<<NB_SCAN1, 512, 0, s2>>>();                               // 4 (s2)
    k_scan2<<<1, 128, 0, s2>>>(NB_SCAN1);                              // 5 (s2)
    k_scan3<<<(NN + 255) / 256, 256, 0, s2>>>();                       // 6 (s2)
    k_scatter<<<(EE + 255) / 256, 256, 0, s2>>>(ei);                   // 7 (s2)
    cudaEventRecord(ev1, s2);

    cudaStreamWaitEvent(0, ev1, 0);              // join: attn needs CSR + proj
    k_attn<<<ATTN_GRID, 256>>>(nullptr);                               // 8: g_h + relu
    k_proj<<<PROJ_GRID, 128>>>(nullptr, 4,                             // 9
        (const float*)d_in[11], (const float*)d_in[13],
        (const float*)d_in[15], (const float*)d_in[17]);
    k_attn<<<ATTN_GRID, 256>>>(out);                                   // 10
}